// round 14
// baseline (speedup 1.0000x reference)
#include <cuda_runtime.h>
#include <cuda_bf16.h>
#include <math.h>
#include <stdint.h>

// Problem constants
#define Bsz 2
#define Hh  64
#define Ww  24
#define Cc  256
#define Pp  8
#define HP  8
#define NHh 8
#define DK  32
#define KV  4
#define NROW (Bsz*Hh*Ww)       // 3072
#define NELEM (NROW*Cc)        // 786432
#define LBLK (HP*Ww)           // 192
#define LKEY (KV*LBLK)         // 768
#define KTOT (25*Cc)           // 6400 conv K
#define NSPLIT 3
#define NCHUNK 200             // 6400 / 32
#define WSZ ((long)Cc*Cc)

#define QK_SCALE (0.17677669529663687f * 1.44269504088896340f)

// ---------------- device scratch ----------------
__device__ float g_buf[11u * NELEM];
__device__ float g_loc[2 * 16 * Cc];
__device__ __nv_bfloat16 g_x_hi[NELEM],   g_x_lo[NELEM];
__device__ __nv_bfloat16 g_act_hi[3u*NELEM], g_act_lo[3u*NELEM];
__device__ __nv_bfloat16 g_ctx_hi[NELEM], g_ctx_lo[NELEM];
__device__ __nv_bfloat16 g_kvg_hi[NELEM], g_kvg_lo[NELEM];
__device__ __nv_bfloat16 g_wt_hi[Cc * KTOT], g_wt_lo[Cc * KTOT];
__device__ __nv_bfloat16 g_w7_hi[7u*Cc*Cc], g_w7_lo[7u*Cc*Cc];

// ---------------- packed f32x2 helpers ----------------
__device__ __forceinline__ unsigned long long pk2(float lo, float hi) {
    unsigned long long r;
    asm("mov.b64 %0, {%1, %2};" : "=l"(r)
        : "r"(__float_as_uint(lo)), "r"(__float_as_uint(hi)));
    return r;
}
__device__ __forceinline__ unsigned long long ffma2(unsigned long long a,
                                                    unsigned long long b,
                                                    unsigned long long c) {
    unsigned long long d;
    asm("fma.rn.f32x2 %0, %1, %2, %3;" : "=l"(d) : "l"(a), "l"(b), "l"(c));
    return d;
}
__device__ __forceinline__ unsigned long long fmul2(unsigned long long a,
                                                    unsigned long long b) {
    unsigned long long d;
    asm("mul.rn.f32x2 %0, %1, %2;" : "=l"(d) : "l"(a), "l"(b));
    return d;
}
__device__ __forceinline__ float2 upk2(unsigned long long v) {
    unsigned int lo, hi;
    asm("mov.b64 {%0, %1}, %2;" : "=r"(lo), "=r"(hi) : "l"(v));
    return make_float2(__uint_as_float(lo), __uint_as_float(hi));
}
__device__ __forceinline__ float ex2f(float x) {
    float r;
    asm("ex2.approx.ftz.f32 %0, %1;" : "=f"(r) : "f"(x));
    return r;
}

// ---------------- warp MMA helpers ----------------
__device__ __forceinline__ uint32_t smem_u32(const void* p) {
    uint32_t a;
    asm("{ .reg .u64 t; cvta.to.shared.u64 t, %1; cvt.u32.u64 %0, t; }"
        : "=r"(a) : "l"(p));
    return a;
}
#define SWZ64(o) ((o) ^ (((o) >> 3) & 0x30))

__device__ __forceinline__ void ldsm4(uint32_t* r, uint32_t addr) {
    asm volatile("ldmatrix.sync.aligned.m8n8.x4.shared.b16 {%0,%1,%2,%3}, [%4];"
                 : "=r"(r[0]), "=r"(r[1]), "=r"(r[2]), "=r"(r[3]) : "r"(addr));
}
__device__ __forceinline__ void mma_bf16(float* c, const uint32_t* a, const uint32_t* b) {
    asm volatile(
        "mma.sync.aligned.m16n8k16.row.col.f32.bf16.bf16.f32 "
        "{%0,%1,%2,%3}, {%4,%5,%6,%7}, {%8,%9}, {%0,%1,%2,%3};"
        : "+f"(c[0]), "+f"(c[1]), "+f"(c[2]), "+f"(c[3])
        : "r"(a[0]), "r"(a[1]), "r"(a[2]), "r"(a[3]), "r"(b[0]), "r"(b[1]));
}

// ================= tensor-core projection GEMM (hi/lo split), r5/r10-proven ===========
struct GemmSetT {
    const __nv_bfloat16 *Ah[3], *Al[3], *Bh[3], *Bl[3];
    const float* bias[3];
    float* C[3];
    __nv_bfloat16 *Ch[3], *Cl[3];   // optional (null => skip)
};

__global__ __launch_bounds__(256, 1)
void gemm_mma_kernel(GemmSetT gs)
{
    __shared__ char smem[32768];
    const uint32_t sb = smem_u32(smem);
    const uint32_t A_HI = sb, A_LO = sb + 8192, B_HI = sb + 16384, B_LO = sb + 24576;

    const int z = blockIdx.z;
    const __nv_bfloat16* __restrict__ Ah = gs.Ah[z];
    const __nv_bfloat16* __restrict__ Al = gs.Al[z];
    const __nv_bfloat16* __restrict__ Bh = gs.Bh[z];
    const __nv_bfloat16* __restrict__ Bl = gs.Bl[z];
    const float* __restrict__ bias = gs.bias[z];
    float* __restrict__ C = gs.C[z];
    __nv_bfloat16* __restrict__ Ch = gs.Ch[z];
    __nv_bfloat16* __restrict__ Cl = gs.Cl[z];

    const int tid  = threadIdx.x;
    const int wid  = tid >> 5;
    const int lane = tid & 31;
    const int m0 = blockIdx.x * 128;
    const int n0 = blockIdx.y * 128;
    const int wm = wid & 3;
    const int wn = wid >> 2;

    int l_row[2], l_seg[2];
#pragma unroll
    for (int i = 0; i < 2; i++) {
        const int idx = tid + 256 * i;
        l_row[i] = idx >> 2;
        l_seg[i] = idx & 3;
    }

    float acc[2][8][4];
#pragma unroll
    for (int i = 0; i < 2; i++)
#pragma unroll
        for (int j = 0; j < 8; j++)
#pragma unroll
            for (int q = 0; q < 4; q++) acc[i][j][q] = 0.f;

    uint4 rAh[2], rAl[2], rBh[2], rBl[2];
#pragma unroll
    for (int i = 0; i < 2; i++) {
        const long aoff = (long)(m0 + l_row[i]) * Cc + l_seg[i] * 8;
        rAh[i] = *(const uint4*)(Ah + aoff);
        rAl[i] = *(const uint4*)(Al + aoff);
        const long boff = (long)(n0 + l_row[i]) * Cc + l_seg[i] * 8;
        rBh[i] = *(const uint4*)(Bh + boff);
        rBl[i] = *(const uint4*)(Bl + boff);
    }

    for (int c = 0; c < 8; c++) {
        __syncthreads();
#pragma unroll
        for (int i = 0; i < 2; i++) {
            const uint32_t so = SWZ64((uint32_t)(l_row[i] * 64 + l_seg[i] * 16));
            *(uint4*)(smem + so)         = rAh[i];
            *(uint4*)(smem + 8192 + so)  = rAl[i];
            *(uint4*)(smem + 16384 + so) = rBh[i];
            *(uint4*)(smem + 24576 + so) = rBl[i];
        }
        __syncthreads();

        if (c + 1 < 8) {
            const int kb = (c + 1) * 32;
#pragma unroll
            for (int i = 0; i < 2; i++) {
                const long aoff = (long)(m0 + l_row[i]) * Cc + kb + l_seg[i] * 8;
                rAh[i] = *(const uint4*)(Ah + aoff);
                rAl[i] = *(const uint4*)(Al + aoff);
                const long boff = (long)(n0 + l_row[i]) * Cc + kb + l_seg[i] * 8;
                rBh[i] = *(const uint4*)(Bh + boff);
                rBl[i] = *(const uint4*)(Bl + boff);
            }
        }

#pragma unroll
        for (int kst = 0; kst < 2; kst++) {
            uint32_t ahi[2][4], alo[2][4];
#pragma unroll
            for (int mh = 0; mh < 2; mh++) {
                const int tile = lane >> 3;
                const int row = wm * 32 + mh * 16 + ((tile & 1) << 3) + (lane & 7);
                const int unit = kst * 2 + (tile >> 1);
                const uint32_t so = SWZ64((uint32_t)(row * 64 + unit * 16));
                ldsm4(ahi[mh], A_HI + so);
                ldsm4(alo[mh], A_LO + so);
            }
            uint32_t bhi[8][2], blo[8][2];
#pragma unroll
            for (int ng = 0; ng < 4; ng++) {
                const int tile = lane >> 3;
                const int row = wn * 64 + ng * 16 + ((tile >> 1) << 3) + (lane & 7);
                const int unit = kst * 2 + (tile & 1);
                const uint32_t so = SWZ64((uint32_t)(row * 64 + unit * 16));
                uint32_t th[4], tl[4];
                ldsm4(th, B_HI + so);
                ldsm4(tl, B_LO + so);
                bhi[ng * 2][0] = th[0]; bhi[ng * 2][1] = th[1];
                bhi[ng * 2 + 1][0] = th[2]; bhi[ng * 2 + 1][1] = th[3];
                blo[ng * 2][0] = tl[0]; blo[ng * 2][1] = tl[1];
                blo[ng * 2 + 1][0] = tl[2]; blo[ng * 2 + 1][1] = tl[3];
            }
#pragma unroll
            for (int mh = 0; mh < 2; mh++)
#pragma unroll
                for (int nt = 0; nt < 8; nt++) {
                    mma_bf16(acc[mh][nt], ahi[mh], bhi[nt]);
                    mma_bf16(acc[mh][nt], alo[mh], bhi[nt]);
                    mma_bf16(acc[mh][nt], ahi[mh], blo[nt]);
                }
        }
    }

    // epilogue: bias + fp32 C + optional bf16 hi/lo decompose
#pragma unroll
    for (int mh = 0; mh < 2; mh++) {
        const int mrow = m0 + wm * 32 + mh * 16 + (lane >> 2);
#pragma unroll
        for (int nt = 0; nt < 8; nt++) {
            const int n = n0 + wn * 64 + nt * 8 + (lane & 3) * 2;
            const float2 bi = *(const float2*)&bias[n];
            const float v0 = acc[mh][nt][0] + bi.x;
            const float v1 = acc[mh][nt][1] + bi.y;
            const float v2 = acc[mh][nt][2] + bi.x;
            const float v3 = acc[mh][nt][3] + bi.y;
            const size_t o0 = (size_t)mrow * Cc + n;
            const size_t o1 = (size_t)(mrow + 8) * Cc + n;
            *(float2*)&C[o0] = make_float2(v0, v1);
            *(float2*)&C[o1] = make_float2(v2, v3);
            if (Ch) {
                const __nv_bfloat16 h0 = __float2bfloat16(v0);
                const __nv_bfloat16 h1 = __float2bfloat16(v1);
                const __nv_bfloat16 h2 = __float2bfloat16(v2);
                const __nv_bfloat16 h3 = __float2bfloat16(v3);
                *(__nv_bfloat162*)&Ch[o0] = __nv_bfloat162(h0, h1);
                *(__nv_bfloat162*)&Ch[o1] = __nv_bfloat162(h2, h3);
                *(__nv_bfloat162*)&Cl[o0] = __nv_bfloat162(
                    __float2bfloat16(v0 - __bfloat162float(h0)),
                    __float2bfloat16(v1 - __bfloat162float(h1)));
                *(__nv_bfloat162*)&Cl[o1] = __nv_bfloat162(
                    __float2bfloat16(v2 - __bfloat162float(h2)),
                    __float2bfloat16(v3 - __bfloat162float(h3)));
            }
        }
    }
}

// ---------------- conv implicit GEMM, 128x128 tile, reg-pipelined K32 (r5/r10-proven) ------
__global__ __launch_bounds__(256, 1)
void conv_mma_kernel(const __nv_bfloat16* __restrict__ a_hi,
                     const __nv_bfloat16* __restrict__ a_lo,
                     const __nv_bfloat16* __restrict__ b_hi,
                     const __nv_bfloat16* __restrict__ b_lo,
                     float* __restrict__ part)
{
    __shared__ char smem[32768];
    const uint32_t sb = smem_u32(smem);
    const uint32_t A_HI = sb, A_LO = sb + 8192, B_HI = sb + 16384, B_LO = sb + 24576;

    const int tid  = threadIdx.x;
    const int wid  = tid >> 5;
    const int lane = tid & 31;
    const int m0 = blockIdx.x * 128;
    const int n0 = blockIdx.y * 128;
    const int z  = blockIdx.z;
    const int cbeg = (z * NCHUNK) / 3;
    const int cend = ((z + 1) * NCHUNK) / 3;

    const int wm = wid & 3;
    const int wn = wid >> 2;

    int a_row[2], a_seg[2], a_h[2], a_w[2];
    long a_base[2];
    int b_rw[2], b_sg[2];
#pragma unroll
    for (int i = 0; i < 2; i++) {
        const int idx = tid + 256 * i;
        a_row[i] = idx >> 2;
        a_seg[i] = idx & 3;
        const int m = m0 + a_row[i];
        const int b = m / (Hh * Ww);
        a_h[i] = (m / Ww) % Hh;
        a_w[i] = m % Ww;
        a_base[i] = (long)b * Hh * Ww * Cc;
        b_rw[i] = idx >> 2;
        b_sg[i] = idx & 3;
    }

    float acc[2][8][4];
#pragma unroll
    for (int i = 0; i < 2; i++)
#pragma unroll
        for (int j = 0; j < 8; j++)
#pragma unroll
            for (int q = 0; q < 4; q++) acc[i][j][q] = 0.f;

    uint4 rAh[2], rAl[2], rBh[2], rBl[2];
    {
        const int kb = cbeg * 32;
        const int patch = kb >> 8;
        const int kh = patch / 5, kw = patch % 5;
        const int ci0 = kb & 255;
#pragma unroll
        for (int i = 0; i < 2; i++) {
            const int hh = a_h[i] + kh - 2;
            const int ww = a_w[i] + kw - 2;
            if (hh >= 0 && hh < Hh && ww >= 0 && ww < Ww) {
                const long off = a_base[i] + ((long)hh * Ww + ww) * Cc + ci0 + a_seg[i] * 8;
                rAh[i] = *(const uint4*)(a_hi + off);
                rAl[i] = *(const uint4*)(a_lo + off);
            } else {
                rAh[i] = make_uint4(0, 0, 0, 0);
                rAl[i] = make_uint4(0, 0, 0, 0);
            }
            const long boff = (long)(n0 + b_rw[i]) * KTOT + kb + b_sg[i] * 8;
            rBh[i] = *(const uint4*)(b_hi + boff);
            rBl[i] = *(const uint4*)(b_lo + boff);
        }
    }

    for (int c = cbeg; c < cend; c++) {
        __syncthreads();
#pragma unroll
        for (int i = 0; i < 2; i++) {
            const uint32_t soA = SWZ64((uint32_t)(a_row[i] * 64 + a_seg[i] * 16));
            *(uint4*)(smem + soA)        = rAh[i];
            *(uint4*)(smem + 8192 + soA) = rAl[i];
            const uint32_t soB = SWZ64((uint32_t)(b_rw[i] * 64 + b_sg[i] * 16));
            *(uint4*)(smem + 16384 + soB) = rBh[i];
            *(uint4*)(smem + 24576 + soB) = rBl[i];
        }
        __syncthreads();

        if (c + 1 < cend) {
            const int kb = (c + 1) * 32;
            const int patch = kb >> 8;
            const int kh = patch / 5, kw = patch % 5;
            const int ci0 = kb & 255;
#pragma unroll
            for (int i = 0; i < 2; i++) {
                const int hh = a_h[i] + kh - 2;
                const int ww = a_w[i] + kw - 2;
                if (hh >= 0 && hh < Hh && ww >= 0 && ww < Ww) {
                    const long off = a_base[i] + ((long)hh * Ww + ww) * Cc + ci0 + a_seg[i] * 8;
                    rAh[i] = *(const uint4*)(a_hi + off);
                    rAl[i] = *(const uint4*)(a_lo + off);
                } else {
                    rAh[i] = make_uint4(0, 0, 0, 0);
                    rAl[i] = make_uint4(0, 0, 0, 0);
                }
                const long boff = (long)(n0 + b_rw[i]) * KTOT + kb + b_sg[i] * 8;
                rBh[i] = *(const uint4*)(b_hi + boff);
                rBl[i] = *(const uint4*)(b_lo + boff);
            }
        }

#pragma unroll
        for (int kst = 0; kst < 2; kst++) {
            uint32_t ahi[2][4], alo[2][4];
#pragma unroll
            for (int mh = 0; mh < 2; mh++) {
                const int tile = lane >> 3;
                const int row = wm * 32 + mh * 16 + ((tile & 1) << 3) + (lane & 7);
                const int unit = kst * 2 + (tile >> 1);
                const uint32_t so = SWZ64((uint32_t)(row * 64 + unit * 16));
                ldsm4(ahi[mh], A_HI + so);
                ldsm4(alo[mh], A_LO + so);
            }
            uint32_t bhi[8][2], blo[8][2];
#pragma unroll
            for (int ng = 0; ng < 4; ng++) {
                const int tile = lane >> 3;
                const int row = wn * 64 + ng * 16 + ((tile >> 1) << 3) + (lane & 7);
                const int unit = kst * 2 + (tile & 1);
                const uint32_t so = SWZ64((uint32_t)(row * 64 + unit * 16));
                uint32_t th[4], tl[4];
                ldsm4(th, B_HI + so);
                ldsm4(tl, B_LO + so);
                bhi[ng * 2][0] = th[0]; bhi[ng * 2][1] = th[1];
                bhi[ng * 2 + 1][0] = th[2]; bhi[ng * 2 + 1][1] = th[3];
                blo[ng * 2][0] = tl[0]; blo[ng * 2][1] = tl[1];
                blo[ng * 2 + 1][0] = tl[2]; blo[ng * 2 + 1][1] = tl[3];
            }
#pragma unroll
            for (int mh = 0; mh < 2; mh++)
#pragma unroll
                for (int nt = 0; nt < 8; nt++) {
                    mma_bf16(acc[mh][nt], ahi[mh], bhi[nt]);
                    mma_bf16(acc[mh][nt], alo[mh], bhi[nt]);
                    mma_bf16(acc[mh][nt], ahi[mh], blo[nt]);
                }
        }
    }

    float* base = part + (size_t)z * NELEM;
#pragma unroll
    for (int mh = 0; mh < 2; mh++) {
        const int mrow = m0 + wm * 32 + mh * 16 + (lane >> 2);
#pragma unroll
        for (int nt = 0; nt < 8; nt++) {
            const int n = n0 + wn * 64 + nt * 8 + (lane & 3) * 2;
            *(float2*)&base[(size_t)mrow * Cc + n] =
                make_float2(acc[mh][nt][0], acc[mh][nt][1]);
            *(float2*)&base[(size_t)(mrow + 8) * Cc + n] =
                make_float2(acc[mh][nt][2], acc[mh][nt][3]);
        }
    }
}

// ---------------- merged decompose: w7 (448) + conv weight (1600) + x (768) ----------------
struct DecompArgs {
    const float* w[7];
    const float* convw;
    const float* x;
};

__global__ void decomp_merged_kernel(DecompArgs da)
{
    const int blk = blockIdx.x;
    const int tid = threadIdx.x;
    const int tx = tid & 31, ty = tid >> 5;

    if (blk < 448) {
        const int z = blk >> 6;
        const int rem = blk & 63;
        const int k0 = (rem & 7) * 32;
        const int n0 = (rem >> 3) * 32;
        const float* __restrict__ w = da.w[z];
        const long zo = (long)z * WSZ;
        __shared__ float tile[32][33];
#pragma unroll
        for (int i = 0; i < 4; i++)
            tile[ty + i * 8][tx] = w[(long)(k0 + ty + i * 8) * Cc + n0 + tx];
        __syncthreads();
#pragma unroll
        for (int i = 0; i < 4; i++) {
            const float v = tile[tx][ty + i * 8];
            const __nv_bfloat16 h = __float2bfloat16(v);
            const long o = zo + (long)(n0 + ty + i * 8) * Cc + k0 + tx;
            g_w7_hi[o] = h;
            g_w7_lo[o] = __float2bfloat16(v - __bfloat162float(h));
        }
    } else if (blk < 2048) {
        const int i2 = blk - 448;
        const int k0 = (i2 % 200) * 32;
        const int n0 = (i2 / 200) * 32;
        __shared__ float tile[32][33];
#pragma unroll
        for (int i = 0; i < 4; i++)
            tile[ty + i * 8][tx] = da.convw[(long)(k0 + ty + i * 8) * Cc + n0 + tx];
        __syncthreads();
#pragma unroll
        for (int i = 0; i < 4; i++) {
            const float v = tile[tx][ty + i * 8];
            const __nv_bfloat16 h = __float2bfloat16(v);
            const long o = (long)(n0 + ty + i * 8) * KTOT + k0 + tx;
            g_wt_hi[o] = h;
            g_wt_lo[o] = __float2bfloat16(v - __bfloat162float(h));
        }
    } else {
        const int idx = (blk - 2048) * 256 + tid;
        if (idx < NELEM / 4) {
            const float4 v = ((const float4*)da.x)[idx];
            const __nv_bfloat16 h0 = __float2bfloat16(v.x), h1 = __float2bfloat16(v.y);
            const __nv_bfloat16 h2 = __float2bfloat16(v.z), h3 = __float2bfloat16(v.w);
            ((__nv_bfloat162*)g_x_hi)[idx * 2]     = __nv_bfloat162(h0, h1);
            ((__nv_bfloat162*)g_x_hi)[idx * 2 + 1] = __nv_bfloat162(h2, h3);
            ((__nv_bfloat162*)g_x_lo)[idx * 2]     = __nv_bfloat162(
                __float2bfloat16(v.x - __bfloat162float(h0)),
                __float2bfloat16(v.y - __bfloat162float(h1)));
            ((__nv_bfloat162*)g_x_lo)[idx * 2 + 1] = __nv_bfloat162(
                __float2bfloat16(v.z - __bfloat162float(h2)),
                __float2bfloat16(v.w - __bfloat162float(h3)));
        }
    }
}

// ---------------- merged: decompose kvg = kp+vp (3072 CTAs) + pool (16 CTAs) ----------------
__global__ void kvg_pool_kernel(const float* __restrict__ kp, const float* __restrict__ vp,
                                const float* __restrict__ qp,
                                __nv_bfloat16* __restrict__ hi, __nv_bfloat16* __restrict__ lo,
                                float* __restrict__ qloc, float* __restrict__ kloc)
{
    const int blk = blockIdx.x;
    const int tid = threadIdx.x;
    if (blk < 3072) {
        const int i = blk * 256 + tid;
        const float v = kp[i] + vp[i];
        const __nv_bfloat16 h = __float2bfloat16(v);
        hi[i] = h;
        lo[i] = __float2bfloat16(v - __bfloat162float(h));
    } else {
        const int bp = blk - 3072;
        const float* qb = qp + (long)bp * LBLK * Cc + tid;
        const float* kb = kp + (long)bp * LBLK * Cc + tid;
        float sq = 0.f, sk = 0.f;
        for (int i = 0; i < LBLK; i++) { sq += qb[i * Cc]; sk += kb[i * Cc]; }
        qloc[bp * Cc + tid] = sq * (1.f / (float)LBLK);
        kloc[bp * Cc + tid] = sk * (1.f / (float)LBLK);
    }
}

// ---------------- attention with inline routing (r10-proven) ----------------
#define KCHUNK 128
__global__ void attention_kernel(const float* __restrict__ q2,
                                 const float* __restrict__ k2,
                                 const float* __restrict__ v2,
                                 const float* __restrict__ qloc,
                                 const float* __restrict__ kloc,
                                 __nv_bfloat16* __restrict__ ctx_hi,
                                 __nv_bfloat16* __restrict__ ctx_lo)
{
    __shared__ float Ks[KCHUNK * DK];
    __shared__ float Vs[KCHUNK * DK];
    __shared__ float Sl[8];
    __shared__ int   Rs[KV];

    const int blk = blockIdx.x;
    const int h = blk % NHh;
    const int p = (blk / NHh) % Pp;
    const int b = blk / (NHh * Pp);
    const int tid = threadIdx.x;
    const int wid = tid >> 5;
    const int lane = tid & 31;

    {
        const float* q = qloc + (b * Pp + p) * Cc;
        const float* k = kloc + (b * Pp + wid) * Cc;
        float partial = 0.f;
#pragma unroll
        for (int c = lane; c < Cc; c += 32) partial += q[c] * k[c];
#pragma unroll
        for (int o = 16; o; o >>= 1) partial += __shfl_xor_sync(0xffffffff, partial, o);
        if (lane == 0) Sl[wid] = partial;
        __syncthreads();
        if (tid == 0) {
            bool used[8] = {};
            for (int t = 0; t < KV; t++) {
                int best = 0; float bv = -1e30f;
                for (int j = 0; j < Pp; j++)
                    if (!used[j] && Sl[j] > bv) { bv = Sl[j]; best = j; }
                used[best] = true;
                Rs[t] = best;
            }
        }
    }

    const bool active = (tid < LBLK);
    unsigned long long qv2[DK / 2], acc2[DK / 2];
    float m = -1e30f, l = 0.f;
    if (active) {
        const float* qrow = q2 + ((long)((b * Pp + p) * LBLK + tid)) * Cc + h * DK;
#pragma unroll
        for (int d2 = 0; d2 < DK / 2; d2++) {
            qv2[d2] = pk2(qrow[2 * d2] * QK_SCALE, qrow[2 * d2 + 1] * QK_SCALE);
            acc2[d2] = 0ull;
        }
    }

    for (int ch = 0; ch < LKEY / KCHUNK; ch++) {
        __syncthreads();
        const int kg0 = ch * KCHUNK;
        for (int i = tid; i < KCHUNK * (DK / 4); i += blockDim.x) {
            const int row = i >> 3;
            const int d4  = (i & 7) * 4;
            const int kg  = kg0 + row;
            const int ks  = kg / LBLK;
            const int rr  = kg - ks * LBLK;
            const int r   = Rs[ks];
            const long base = ((long)(b * Pp + r) * LBLK + rr) * Cc + h * DK + d4;
            *(float4*)&Ks[row * DK + d4] = *(const float4*)&k2[base];
            *(float4*)&Vs[row * DK + d4] = *(const float4*)&v2[base];
        }
        __syncthreads();
        if (active) {
            for (int k = 0; k < KCHUNK; k++) {
                const unsigned long long* kr = (const unsigned long long*)&Ks[k * DK];
                unsigned long long s0 = 0ull, s1 = 0ull, s2 = 0ull, s3 = 0ull;
#pragma unroll
                for (int d2 = 0; d2 < DK / 2; d2 += 4) {
                    s0 = ffma2(qv2[d2 + 0], kr[d2 + 0], s0);
                    s1 = ffma2(qv2[d2 + 1], kr[d2 + 1], s1);
                    s2 = ffma2(qv2[d2 + 2], kr[d2 + 2], s2);
                    s3 = ffma2(qv2[d2 + 3], kr[d2 + 3], s3);
                }
                const float2 f0 = upk2(s0), f1 = upk2(s1), f2 = upk2(s2), f3 = upk2(s3);
                const float s = ((f0.x + f0.y) + (f1.x + f1.y)) + ((f2.x + f2.y) + (f3.x + f3.y));
                const float mnew = fmaxf(m, s);
                const float corr = ex2f(m - mnew);
                const float pe   = ex2f(s - mnew);
                l = fmaf(l, corr, pe);
                const unsigned long long cc = pk2(corr, corr);
                const unsigned long long pp = pk2(pe, pe);
                const unsigned long long* vr = (const unsigned long long*)&Vs[k * DK];
#pragma unroll
                for (int d2 = 0; d2 < DK / 2; d2++)
                    acc2[d2] = ffma2(acc2[d2], cc, fmul2(pp, vr[d2]));
                m = mnew;
            }
        }
    }

    if (active) {
        const float inv = 1.0f / l;
        const long base = ((long)((b * Pp + p) * LBLK + tid)) * Cc + h * DK;
#pragma unroll
        for (int d2 = 0; d2 < DK / 2; d2++) {
            float2 f = upk2(acc2[d2]);
            const float v0 = f.x * inv, v1 = f.y * inv;
            const __nv_bfloat16 h0 = __float2bfloat16(v0);
            const __nv_bfloat16 h1 = __float2bfloat16(v1);
            *(__nv_bfloat162*)&ctx_hi[base + 2 * d2] = __nv_bfloat162(h0, h1);
            *(__nv_bfloat162*)&ctx_lo[base + 2 * d2] = __nv_bfloat162(
                __float2bfloat16(v0 - __bfloat162float(h0)),
                __float2bfloat16(v1 - __bfloat162float(h1)));
        }
    }
}

// ---------------- fused residual add + LayerNorm ----------------
__global__ void add_ln_kernel(const float* __restrict__ a, const float* __restrict__ bsrc,
                              const float* __restrict__ g, const float* __restrict__ beta,
                              float* __restrict__ out)
{
    const int mrow = blockIdx.x;
    const int c = threadIdx.x;
    __shared__ float red[Cc];
    const float v = a[(long)mrow * Cc + c] + bsrc[(long)mrow * Cc + c];
    red[c] = v;
    __syncthreads();
    for (int s = Cc / 2; s > 0; s >>= 1) {
        if (c < s) red[c] += red[c + s];
        __syncthreads();
    }
    const float mean = red[0] * (1.f / (float)Cc);
    __syncthreads();
    const float d = v - mean;
    red[c] = d * d;
    __syncthreads();
    for (int s = Cc / 2; s > 0; s >>= 1) {
        if (c < s) red[c] += red[c + s];
        __syncthreads();
    }
    const float var = red[0] * (1.f / (float)Cc);
    out[(long)mrow * Cc + c] = d * rsqrtf(var + 1e-5f) * g[c] + beta[c];
}

__global__ void add_lnK_kernel(const float* __restrict__ a, const float* __restrict__ pbase,
                               const float* __restrict__ cb,
                               const float* __restrict__ g, const float* __restrict__ beta,
                               float* __restrict__ out)
{
    const int mrow = blockIdx.x;
    const int c = threadIdx.x;
    __shared__ float red[Cc];
    const long off = (long)mrow * Cc + c;
    float v = a[off] + cb[c];
#pragma unroll
    for (int s = 0; s < NSPLIT; s++) v += pbase[off + (size_t)s * NELEM];
    red[c] = v;
    __syncthreads();
    for (int s = Cc / 2; s > 0; s >>= 1) {
        if (c < s) red[c] += red[c + s];
        __syncthreads();
    }
    const float mean = red[0] * (1.f / (float)Cc);
    __syncthreads();
    const float d = v - mean;
    red[c] = d * d;
    __syncthreads();
    for (int s = Cc / 2; s > 0; s >>= 1) {
        if (c < s) red[c] += red[c + s];
        __syncthreads();
    }
    const float var = red[0] * (1.f / (float)Cc);
    out[off] = d * rsqrtf(var + 1e-5f) * g[c] + beta[c];
}

// ---------------- launcher (stream-forked: conv overlaps attention chain) ----------------
extern "C" void kernel_launch(void* const* d_in, const int* in_sizes, int n_in,
                              void* d_out, int out_size)
{
    const float* x        = (const float*)d_in[0];
    const float* wq_proj  = (const float*)d_in[1];
    const float* bq_proj  = (const float*)d_in[2];
    const float* wk_proj  = (const float*)d_in[3];
    const float* bk_proj  = (const float*)d_in[4];
    const float* wv_proj  = (const float*)d_in[5];
    const float* bv_proj  = (const float*)d_in[6];
    const float* wq_a     = (const float*)d_in[7];
    const float* bq_a     = (const float*)d_in[8];
    const float* wk_a     = (const float*)d_in[9];
    const float* bk_a     = (const float*)d_in[10];
    const float* wv_a     = (const float*)d_in[11];
    const float* bv_a     = (const float*)d_in[12];
    const float* wo_a     = (const float*)d_in[13];
    const float* bo_a     = (const float*)d_in[14];
    const float* conv_w   = (const float*)d_in[15];
    const float* conv_b   = (const float*)d_in[16];
    const float* ln1_g    = (const float*)d_in[17];
    const float* ln1_b    = (const float*)d_in[18];
    const float* ln2_g    = (const float*)d_in[19];
    const float* ln2_b    = (const float*)d_in[20];
    float* out = (float*)d_out;

    float* buf = nullptr;   cudaGetSymbolAddress((void**)&buf, g_buf);
    float* loc = nullptr;   cudaGetSymbolAddress((void**)&loc, g_loc);
    __nv_bfloat16 *xh, *xl, *ah, *al, *cxh, *cxl, *kvh, *kvl, *wth, *wtl, *w7h, *w7l;
    cudaGetSymbolAddress((void**)&xh,  g_x_hi);
    cudaGetSymbolAddress((void**)&xl,  g_x_lo);
    cudaGetSymbolAddress((void**)&ah,  g_act_hi);
    cudaGetSymbolAddress((void**)&al,  g_act_lo);
    cudaGetSymbolAddress((void**)&cxh, g_ctx_hi);
    cudaGetSymbolAddress((void**)&cxl, g_ctx_lo);
    cudaGetSymbolAddress((void**)&kvh, g_kvg_hi);
    cudaGetSymbolAddress((void**)&kvl, g_kvg_lo);
    cudaGetSymbolAddress((void**)&wth, g_wt_hi);
    cudaGetSymbolAddress((void**)&wtl, g_wt_lo);
    cudaGetSymbolAddress((void**)&w7h, g_w7_hi);
    cudaGetSymbolAddress((void**)&w7l, g_w7_lo);

    float* qp   = buf + 0l * NELEM;
    float* kp   = buf + 1l * NELEM;
    float* vp   = buf + 2l * NELEM;
    float* xres = buf + 3l * NELEM;
    float* q2   = buf + 4l * NELEM;
    float* k2   = buf + 5l * NELEM;
    float* v2   = buf + 6l * NELEM;
    float* rout = buf + 7l * NELEM;
    float* cnvp = buf + 8l * NELEM;
    float* qloc = loc;
    float* kloc = loc + 16 * Cc;

    // side stream + events for the fork (created per call, not destroyed:
    // the graph holds its own representation; harness calls this a bounded
    // number of times. No device-memory allocation involved.)
    cudaStream_t s2;
    cudaStreamCreateWithFlags(&s2, cudaStreamNonBlocking);
    cudaEvent_t evFork, evJoin;
    cudaEventCreateWithFlags(&evFork, cudaEventDisableTiming);
    cudaEventCreateWithFlags(&evJoin, cudaEventDisableTiming);

    // 1: all decomposition in one tight launch
    {
        DecompArgs da;
        da.w[0] = wq_proj; da.w[1] = wk_proj; da.w[2] = wv_proj;
        da.w[3] = wq_a;    da.w[4] = wk_a;    da.w[5] = wv_a;    da.w[6] = wo_a;
        da.convw = conv_w; da.x = x;
        decomp_merged_kernel<<<2816, 256>>>(da);
    }

    // 2: q/k/v block projections
    {
        GemmSetT gs;
        for (int i = 0; i < 3; i++) {
            gs.Ah[i] = xh; gs.Al[i] = xl;
            gs.Bh[i] = w7h + i * WSZ; gs.Bl[i] = w7l + i * WSZ;
            gs.Ch[i] = ah + (long)i * NELEM; gs.Cl[i] = al + (long)i * NELEM;
        }
        gs.bias[0] = bq_proj; gs.bias[1] = bk_proj; gs.bias[2] = bv_proj;
        gs.C[0] = qp; gs.C[1] = kp; gs.C[2] = vp;
        gemm_mma_kernel<<<dim3(NROW / 128, Cc / 128, 3), 256>>>(gs);
    }

    // 3: kvg decompose + pool
    kvg_pool_kernel<<<3072 + 16, 256>>>(kp, vp, qp, kvh, kvl, qloc, kloc);

    // --- fork: conv branch on s2, attention branch continues on default ---
    cudaEventRecord(evFork, 0);
    cudaStreamWaitEvent(s2, evFork, 0);

    // conv branch (s2)
    conv_mma_kernel<<<dim3(NROW / 128, Cc / 128, NSPLIT), 256, 0, s2>>>(
        kvh, kvl, wth, wtl, cnvp);
    cudaEventRecord(evJoin, s2);

    // attention branch (default stream)
    {
        GemmSetT gs;
        for (int i = 0; i < 3; i++) {
            gs.Ah[i] = ah + (long)i * NELEM; gs.Al[i] = al + (long)i * NELEM;
            gs.Bh[i] = w7h + (3 + i) * WSZ;  gs.Bl[i] = w7l + (3 + i) * WSZ;
            gs.Ch[i] = nullptr; gs.Cl[i] = nullptr;
        }
        gs.bias[0] = bq_a; gs.bias[1] = bk_a; gs.bias[2] = bv_a;
        gs.C[0] = q2; gs.C[1] = k2; gs.C[2] = v2;
        gemm_mma_kernel<<<dim3(NROW / 128, Cc / 128, 3), 256>>>(gs);
    }

    attention_kernel<<<Bsz * Pp * NHh, 256>>>(q2, k2, v2, qloc, kloc, cxh, cxl);

    {
        GemmSetT gs;
        gs.Ah[0] = cxh; gs.Al[0] = cxl;
        gs.Bh[0] = w7h + 6 * WSZ; gs.Bl[0] = w7l + 6 * WSZ;
        gs.bias[0] = bo_a;
        gs.C[0] = rout;
        gs.Ch[0] = nullptr; gs.Cl[0] = nullptr;
        for (int i = 1; i < 3; i++) {
            gs.Ah[i] = cxh; gs.Al[i] = cxl;
            gs.Bh[i] = w7h; gs.Bl[i] = w7l;
            gs.bias[i] = bo_a; gs.C[i] = rout;
            gs.Ch[i] = nullptr; gs.Cl[i] = nullptr;
        }
        gemm_mma_kernel<<<dim3(NROW / 128, Cc / 128, 1), 256>>>(gs);
    }

    // LN1 (only needs x + rout)
    add_ln_kernel<<<NROW, Cc>>>(x, rout, ln1_g, ln1_b, xres);

    // --- join: final LN needs conv partials ---
    cudaStreamWaitEvent(0, evJoin, 0);
    add_lnK_kernel<<<NROW, Cc>>>(xres, cnvp, conv_b, ln2_g, ln2_b, out);
}

// round 15
// speedup vs baseline: 1.5483x; 1.5483x over previous
#include <cuda_runtime.h>
#include <cuda_bf16.h>
#include <math.h>
#include <stdint.h>

// Problem constants
#define Bsz 2
#define Hh  64
#define Ww  24
#define Cc  256
#define Pp  8
#define HP  8
#define NHh 8
#define DK  32
#define KV  4
#define NROW (Bsz*Hh*Ww)       // 3072
#define NELEM (NROW*Cc)        // 786432
#define LBLK (HP*Ww)           // 192
#define LKEY (KV*LBLK)         // 768
#define KTOT (25*Cc)           // 6400 conv K
#define NSPLIT 3
#define NCHUNK 200             // 6400 / 32
#define WSZ ((long)Cc*Cc)

#define QK_SCALE (0.17677669529663687f * 1.44269504088896340f)

// ---------------- device scratch ----------------
// fp32 slots: 0:qp 1:kp 2:vp 3:xres 4:q2 5:k2 6:v2 7:rout 8..10:conv partials
__device__ float g_buf[11u * NELEM];
__device__ float g_loc[2 * 16 * Cc];
__device__ __nv_bfloat16 g_x_hi[NELEM],   g_x_lo[NELEM];
__device__ __nv_bfloat16 g_act_hi[3u*NELEM], g_act_lo[3u*NELEM];
__device__ __nv_bfloat16 g_ctx_hi[NELEM], g_ctx_lo[NELEM];
__device__ __nv_bfloat16 g_kvg_hi[NELEM], g_kvg_lo[NELEM];
__device__ __nv_bfloat16 g_wt_hi[Cc * KTOT], g_wt_lo[Cc * KTOT];
__device__ __nv_bfloat16 g_w7_hi[7u*Cc*Cc], g_w7_lo[7u*Cc*Cc];

// ---------------- packed f32x2 helpers ----------------
__device__ __forceinline__ unsigned long long pk2(float lo, float hi) {
    unsigned long long r;
    asm("mov.b64 %0, {%1, %2};" : "=l"(r)
        : "r"(__float_as_uint(lo)), "r"(__float_as_uint(hi)));
    return r;
}
__device__ __forceinline__ unsigned long long ffma2(unsigned long long a,
                                                    unsigned long long b,
                                                    unsigned long long c) {
    unsigned long long d;
    asm("fma.rn.f32x2 %0, %1, %2, %3;" : "=l"(d) : "l"(a), "l"(b), "l"(c));
    return d;
}
__device__ __forceinline__ unsigned long long fmul2(unsigned long long a,
                                                    unsigned long long b) {
    unsigned long long d;
    asm("mul.rn.f32x2 %0, %1, %2;" : "=l"(d) : "l"(a), "l"(b));
    return d;
}
__device__ __forceinline__ float2 upk2(unsigned long long v) {
    unsigned int lo, hi;
    asm("mov.b64 {%0, %1}, %2;" : "=r"(lo), "=r"(hi) : "l"(v));
    return make_float2(__uint_as_float(lo), __uint_as_float(hi));
}
__device__ __forceinline__ float ex2f(float x) {
    float r;
    asm("ex2.approx.ftz.f32 %0, %1;" : "=f"(r) : "f"(x));
    return r;
}

// ---------------- warp MMA helpers ----------------
__device__ __forceinline__ uint32_t smem_u32(const void* p) {
    uint32_t a;
    asm("{ .reg .u64 t; cvta.to.shared.u64 t, %1; cvt.u32.u64 %0, t; }"
        : "=r"(a) : "l"(p));
    return a;
}
#define SWZ64(o) ((o) ^ (((o) >> 3) & 0x30))

__device__ __forceinline__ void ldsm4(uint32_t* r, uint32_t addr) {
    asm volatile("ldmatrix.sync.aligned.m8n8.x4.shared.b16 {%0,%1,%2,%3}, [%4];"
                 : "=r"(r[0]), "=r"(r[1]), "=r"(r[2]), "=r"(r[3]) : "r"(addr));
}
__device__ __forceinline__ void mma_bf16(float* c, const uint32_t* a, const uint32_t* b) {
    asm volatile(
        "mma.sync.aligned.m16n8k16.row.col.f32.bf16.bf16.f32 "
        "{%0,%1,%2,%3}, {%4,%5,%6,%7}, {%8,%9}, {%0,%1,%2,%3};"
        : "+f"(c[0]), "+f"(c[1]), "+f"(c[2]), "+f"(c[3])
        : "r"(a[0]), "r"(a[1]), "r"(a[2]), "r"(a[3]), "r"(b[0]), "r"(b[1]));
}

// ================= tensor-core projection GEMM (hi/lo split), r5/r10-proven ===========
struct GemmSetT {
    const __nv_bfloat16 *Ah[3], *Al[3], *Bh[3], *Bl[3];
    const float* bias[3];
    float* C[3];
    __nv_bfloat16 *Ch[3], *Cl[3];   // optional (null => skip)
};

__global__ __launch_bounds__(256, 1)
void gemm_mma_kernel(GemmSetT gs)
{
    __shared__ char smem[32768];
    const uint32_t sb = smem_u32(smem);
    const uint32_t A_HI = sb, A_LO = sb + 8192, B_HI = sb + 16384, B_LO = sb + 24576;

    const int z = blockIdx.z;
    const __nv_bfloat16* __restrict__ Ah = gs.Ah[z];
    const __nv_bfloat16* __restrict__ Al = gs.Al[z];
    const __nv_bfloat16* __restrict__ Bh = gs.Bh[z];
    const __nv_bfloat16* __restrict__ Bl = gs.Bl[z];
    const float* __restrict__ bias = gs.bias[z];
    float* __restrict__ C = gs.C[z];
    __nv_bfloat16* __restrict__ Ch = gs.Ch[z];
    __nv_bfloat16* __restrict__ Cl = gs.Cl[z];

    const int tid  = threadIdx.x;
    const int wid  = tid >> 5;
    const int lane = tid & 31;
    const int m0 = blockIdx.x * 128;
    const int n0 = blockIdx.y * 128;
    const int wm = wid & 3;
    const int wn = wid >> 2;

    int l_row[2], l_seg[2];
#pragma unroll
    for (int i = 0; i < 2; i++) {
        const int idx = tid + 256 * i;
        l_row[i] = idx >> 2;
        l_seg[i] = idx & 3;
    }

    float acc[2][8][4];
#pragma unroll
    for (int i = 0; i < 2; i++)
#pragma unroll
        for (int j = 0; j < 8; j++)
#pragma unroll
            for (int q = 0; q < 4; q++) acc[i][j][q] = 0.f;

    uint4 rAh[2], rAl[2], rBh[2], rBl[2];
#pragma unroll
    for (int i = 0; i < 2; i++) {
        const long aoff = (long)(m0 + l_row[i]) * Cc + l_seg[i] * 8;
        rAh[i] = *(const uint4*)(Ah + aoff);
        rAl[i] = *(const uint4*)(Al + aoff);
        const long boff = (long)(n0 + l_row[i]) * Cc + l_seg[i] * 8;
        rBh[i] = *(const uint4*)(Bh + boff);
        rBl[i] = *(const uint4*)(Bl + boff);
    }

    for (int c = 0; c < 8; c++) {
        __syncthreads();
#pragma unroll
        for (int i = 0; i < 2; i++) {
            const uint32_t so = SWZ64((uint32_t)(l_row[i] * 64 + l_seg[i] * 16));
            *(uint4*)(smem + so)         = rAh[i];
            *(uint4*)(smem + 8192 + so)  = rAl[i];
            *(uint4*)(smem + 16384 + so) = rBh[i];
            *(uint4*)(smem + 24576 + so) = rBl[i];
        }
        __syncthreads();

        if (c + 1 < 8) {
            const int kb = (c + 1) * 32;
#pragma unroll
            for (int i = 0; i < 2; i++) {
                const long aoff = (long)(m0 + l_row[i]) * Cc + kb + l_seg[i] * 8;
                rAh[i] = *(const uint4*)(Ah + aoff);
                rAl[i] = *(const uint4*)(Al + aoff);
                const long boff = (long)(n0 + l_row[i]) * Cc + kb + l_seg[i] * 8;
                rBh[i] = *(const uint4*)(Bh + boff);
                rBl[i] = *(const uint4*)(Bl + boff);
            }
        }

#pragma unroll
        for (int kst = 0; kst < 2; kst++) {
            uint32_t ahi[2][4], alo[2][4];
#pragma unroll
            for (int mh = 0; mh < 2; mh++) {
                const int tile = lane >> 3;
                const int row = wm * 32 + mh * 16 + ((tile & 1) << 3) + (lane & 7);
                const int unit = kst * 2 + (tile >> 1);
                const uint32_t so = SWZ64((uint32_t)(row * 64 + unit * 16));
                ldsm4(ahi[mh], A_HI + so);
                ldsm4(alo[mh], A_LO + so);
            }
            uint32_t bhi[8][2], blo[8][2];
#pragma unroll
            for (int ng = 0; ng < 4; ng++) {
                const int tile = lane >> 3;
                const int row = wn * 64 + ng * 16 + ((tile >> 1) << 3) + (lane & 7);
                const int unit = kst * 2 + (tile & 1);
                const uint32_t so = SWZ64((uint32_t)(row * 64 + unit * 16));
                uint32_t th[4], tl[4];
                ldsm4(th, B_HI + so);
                ldsm4(tl, B_LO + so);
                bhi[ng * 2][0] = th[0]; bhi[ng * 2][1] = th[1];
                bhi[ng * 2 + 1][0] = th[2]; bhi[ng * 2 + 1][1] = th[3];
                blo[ng * 2][0] = tl[0]; blo[ng * 2][1] = tl[1];
                blo[ng * 2 + 1][0] = tl[2]; blo[ng * 2 + 1][1] = tl[3];
            }
#pragma unroll
            for (int mh = 0; mh < 2; mh++)
#pragma unroll
                for (int nt = 0; nt < 8; nt++) {
                    mma_bf16(acc[mh][nt], ahi[mh], bhi[nt]);
                    mma_bf16(acc[mh][nt], alo[mh], bhi[nt]);
                    mma_bf16(acc[mh][nt], ahi[mh], blo[nt]);
                }
        }
    }

    // epilogue: bias + fp32 C + optional bf16 hi/lo decompose
#pragma unroll
    for (int mh = 0; mh < 2; mh++) {
        const int mrow = m0 + wm * 32 + mh * 16 + (lane >> 2);
#pragma unroll
        for (int nt = 0; nt < 8; nt++) {
            const int n = n0 + wn * 64 + nt * 8 + (lane & 3) * 2;
            const float2 bi = *(const float2*)&bias[n];
            const float v0 = acc[mh][nt][0] + bi.x;
            const float v1 = acc[mh][nt][1] + bi.y;
            const float v2 = acc[mh][nt][2] + bi.x;
            const float v3 = acc[mh][nt][3] + bi.y;
            const size_t o0 = (size_t)mrow * Cc + n;
            const size_t o1 = (size_t)(mrow + 8) * Cc + n;
            *(float2*)&C[o0] = make_float2(v0, v1);
            *(float2*)&C[o1] = make_float2(v2, v3);
            if (Ch) {
                const __nv_bfloat16 h0 = __float2bfloat16(v0);
                const __nv_bfloat16 h1 = __float2bfloat16(v1);
                const __nv_bfloat16 h2 = __float2bfloat16(v2);
                const __nv_bfloat16 h3 = __float2bfloat16(v3);
                *(__nv_bfloat162*)&Ch[o0] = __nv_bfloat162(h0, h1);
                *(__nv_bfloat162*)&Ch[o1] = __nv_bfloat162(h2, h3);
                *(__nv_bfloat162*)&Cl[o0] = __nv_bfloat162(
                    __float2bfloat16(v0 - __bfloat162float(h0)),
                    __float2bfloat16(v1 - __bfloat162float(h1)));
                *(__nv_bfloat162*)&Cl[o1] = __nv_bfloat162(
                    __float2bfloat16(v2 - __bfloat162float(h2)),
                    __float2bfloat16(v3 - __bfloat162float(h3)));
            }
        }
    }
}

// ---------------- conv implicit GEMM, 128x128 tile, reg-pipelined K32 (r5/r10-proven) ------
__global__ __launch_bounds__(256, 1)
void conv_mma_kernel(const __nv_bfloat16* __restrict__ a_hi,
                     const __nv_bfloat16* __restrict__ a_lo,
                     const __nv_bfloat16* __restrict__ b_hi,
                     const __nv_bfloat16* __restrict__ b_lo,
                     float* __restrict__ part)
{
    __shared__ char smem[32768];
    const uint32_t sb = smem_u32(smem);
    const uint32_t A_HI = sb, A_LO = sb + 8192, B_HI = sb + 16384, B_LO = sb + 24576;

    const int tid  = threadIdx.x;
    const int wid  = tid >> 5;
    const int lane = tid & 31;
    const int m0 = blockIdx.x * 128;
    const int n0 = blockIdx.y * 128;
    const int z  = blockIdx.z;
    const int cbeg = (z * NCHUNK) / 3;
    const int cend = ((z + 1) * NCHUNK) / 3;

    const int wm = wid & 3;
    const int wn = wid >> 2;

    int a_row[2], a_seg[2], a_h[2], a_w[2];
    long a_base[2];
    int b_rw[2], b_sg[2];
#pragma unroll
    for (int i = 0; i < 2; i++) {
        const int idx = tid + 256 * i;
        a_row[i] = idx >> 2;
        a_seg[i] = idx & 3;
        const int m = m0 + a_row[i];
        const int b = m / (Hh * Ww);
        a_h[i] = (m / Ww) % Hh;
        a_w[i] = m % Ww;
        a_base[i] = (long)b * Hh * Ww * Cc;
        b_rw[i] = idx >> 2;
        b_sg[i] = idx & 3;
    }

    float acc[2][8][4];
#pragma unroll
    for (int i = 0; i < 2; i++)
#pragma unroll
        for (int j = 0; j < 8; j++)
#pragma unroll
            for (int q = 0; q < 4; q++) acc[i][j][q] = 0.f;

    uint4 rAh[2], rAl[2], rBh[2], rBl[2];
    {
        const int kb = cbeg * 32;
        const int patch = kb >> 8;
        const int kh = patch / 5, kw = patch % 5;
        const int ci0 = kb & 255;
#pragma unroll
        for (int i = 0; i < 2; i++) {
            const int hh = a_h[i] + kh - 2;
            const int ww = a_w[i] + kw - 2;
            if (hh >= 0 && hh < Hh && ww >= 0 && ww < Ww) {
                const long off = a_base[i] + ((long)hh * Ww + ww) * Cc + ci0 + a_seg[i] * 8;
                rAh[i] = *(const uint4*)(a_hi + off);
                rAl[i] = *(const uint4*)(a_lo + off);
            } else {
                rAh[i] = make_uint4(0, 0, 0, 0);
                rAl[i] = make_uint4(0, 0, 0, 0);
            }
            const long boff = (long)(n0 + b_rw[i]) * KTOT + kb + b_sg[i] * 8;
            rBh[i] = *(const uint4*)(b_hi + boff);
            rBl[i] = *(const uint4*)(b_lo + boff);
        }
    }

    for (int c = cbeg; c < cend; c++) {
        __syncthreads();
#pragma unroll
        for (int i = 0; i < 2; i++) {
            const uint32_t soA = SWZ64((uint32_t)(a_row[i] * 64 + a_seg[i] * 16));
            *(uint4*)(smem + soA)        = rAh[i];
            *(uint4*)(smem + 8192 + soA) = rAl[i];
            const uint32_t soB = SWZ64((uint32_t)(b_rw[i] * 64 + b_sg[i] * 16));
            *(uint4*)(smem + 16384 + soB) = rBh[i];
            *(uint4*)(smem + 24576 + soB) = rBl[i];
        }
        __syncthreads();

        if (c + 1 < cend) {
            const int kb = (c + 1) * 32;
            const int patch = kb >> 8;
            const int kh = patch / 5, kw = patch % 5;
            const int ci0 = kb & 255;
#pragma unroll
            for (int i = 0; i < 2; i++) {
                const int hh = a_h[i] + kh - 2;
                const int ww = a_w[i] + kw - 2;
                if (hh >= 0 && hh < Hh && ww >= 0 && ww < Ww) {
                    const long off = a_base[i] + ((long)hh * Ww + ww) * Cc + ci0 + a_seg[i] * 8;
                    rAh[i] = *(const uint4*)(a_hi + off);
                    rAl[i] = *(const uint4*)(a_lo + off);
                } else {
                    rAh[i] = make_uint4(0, 0, 0, 0);
                    rAl[i] = make_uint4(0, 0, 0, 0);
                }
                const long boff = (long)(n0 + b_rw[i]) * KTOT + kb + b_sg[i] * 8;
                rBh[i] = *(const uint4*)(b_hi + boff);
                rBl[i] = *(const uint4*)(b_lo + boff);
            }
        }

#pragma unroll
        for (int kst = 0; kst < 2; kst++) {
            uint32_t ahi[2][4], alo[2][4];
#pragma unroll
            for (int mh = 0; mh < 2; mh++) {
                const int tile = lane >> 3;
                const int row = wm * 32 + mh * 16 + ((tile & 1) << 3) + (lane & 7);
                const int unit = kst * 2 + (tile >> 1);
                const uint32_t so = SWZ64((uint32_t)(row * 64 + unit * 16));
                ldsm4(ahi[mh], A_HI + so);
                ldsm4(alo[mh], A_LO + so);
            }
            uint32_t bhi[8][2], blo[8][2];
#pragma unroll
            for (int ng = 0; ng < 4; ng++) {
                const int tile = lane >> 3;
                const int row = wn * 64 + ng * 16 + ((tile >> 1) << 3) + (lane & 7);
                const int unit = kst * 2 + (tile & 1);
                const uint32_t so = SWZ64((uint32_t)(row * 64 + unit * 16));
                uint32_t th[4], tl[4];
                ldsm4(th, B_HI + so);
                ldsm4(tl, B_LO + so);
                bhi[ng * 2][0] = th[0]; bhi[ng * 2][1] = th[1];
                bhi[ng * 2 + 1][0] = th[2]; bhi[ng * 2 + 1][1] = th[3];
                blo[ng * 2][0] = tl[0]; blo[ng * 2][1] = tl[1];
                blo[ng * 2 + 1][0] = tl[2]; blo[ng * 2 + 1][1] = tl[3];
            }
#pragma unroll
            for (int mh = 0; mh < 2; mh++)
#pragma unroll
                for (int nt = 0; nt < 8; nt++) {
                    mma_bf16(acc[mh][nt], ahi[mh], bhi[nt]);
                    mma_bf16(acc[mh][nt], alo[mh], bhi[nt]);
                    mma_bf16(acc[mh][nt], ahi[mh], blo[nt]);
                }
        }
    }

    float* base = part + (size_t)z * NELEM;
#pragma unroll
    for (int mh = 0; mh < 2; mh++) {
        const int mrow = m0 + wm * 32 + mh * 16 + (lane >> 2);
#pragma unroll
        for (int nt = 0; nt < 8; nt++) {
            const int n = n0 + wn * 64 + nt * 8 + (lane & 3) * 2;
            *(float2*)&base[(size_t)mrow * Cc + n] =
                make_float2(acc[mh][nt][0], acc[mh][nt][1]);
            *(float2*)&base[(size_t)(mrow + 8) * Cc + n] =
                make_float2(acc[mh][nt][2], acc[mh][nt][3]);
        }
    }
}

// ---------------- merged decompose: w7 (448) + conv weight (1600) + x (768) ----------------
struct DecompArgs {
    const float* w[7];
    const float* convw;
    const float* x;
};

__global__ void decomp_merged_kernel(DecompArgs da)
{
    const int blk = blockIdx.x;
    const int tid = threadIdx.x;
    const int tx = tid & 31, ty = tid >> 5;

    if (blk < 448) {
        const int z = blk >> 6;
        const int rem = blk & 63;
        const int k0 = (rem & 7) * 32;
        const int n0 = (rem >> 3) * 32;
        const float* __restrict__ w = da.w[z];
        const long zo = (long)z * WSZ;
        __shared__ float tile[32][33];
#pragma unroll
        for (int i = 0; i < 4; i++)
            tile[ty + i * 8][tx] = w[(long)(k0 + ty + i * 8) * Cc + n0 + tx];
        __syncthreads();
#pragma unroll
        for (int i = 0; i < 4; i++) {
            const float v = tile[tx][ty + i * 8];
            const __nv_bfloat16 h = __float2bfloat16(v);
            const long o = zo + (long)(n0 + ty + i * 8) * Cc + k0 + tx;
            g_w7_hi[o] = h;
            g_w7_lo[o] = __float2bfloat16(v - __bfloat162float(h));
        }
    } else if (blk < 2048) {
        const int i2 = blk - 448;
        const int k0 = (i2 % 200) * 32;
        const int n0 = (i2 / 200) * 32;
        __shared__ float tile[32][33];
#pragma unroll
        for (int i = 0; i < 4; i++)
            tile[ty + i * 8][tx] = da.convw[(long)(k0 + ty + i * 8) * Cc + n0 + tx];
        __syncthreads();
#pragma unroll
        for (int i = 0; i < 4; i++) {
            const float v = tile[tx][ty + i * 8];
            const __nv_bfloat16 h = __float2bfloat16(v);
            const long o = (long)(n0 + ty + i * 8) * KTOT + k0 + tx;
            g_wt_hi[o] = h;
            g_wt_lo[o] = __float2bfloat16(v - __bfloat162float(h));
        }
    } else {
        const int idx = (blk - 2048) * 256 + tid;
        if (idx < NELEM / 4) {
            const float4 v = ((const float4*)da.x)[idx];
            const __nv_bfloat16 h0 = __float2bfloat16(v.x), h1 = __float2bfloat16(v.y);
            const __nv_bfloat16 h2 = __float2bfloat16(v.z), h3 = __float2bfloat16(v.w);
            ((__nv_bfloat162*)g_x_hi)[idx * 2]     = __nv_bfloat162(h0, h1);
            ((__nv_bfloat162*)g_x_hi)[idx * 2 + 1] = __nv_bfloat162(h2, h3);
            ((__nv_bfloat162*)g_x_lo)[idx * 2]     = __nv_bfloat162(
                __float2bfloat16(v.x - __bfloat162float(h0)),
                __float2bfloat16(v.y - __bfloat162float(h1)));
            ((__nv_bfloat162*)g_x_lo)[idx * 2 + 1] = __nv_bfloat162(
                __float2bfloat16(v.z - __bfloat162float(h2)),
                __float2bfloat16(v.w - __bfloat162float(h3)));
        }
    }
}

// ---------------- merged: decompose kvg = kp+vp (3072 CTAs) + pool (16 CTAs) ----------------
__global__ void kvg_pool_kernel(const float* __restrict__ kp, const float* __restrict__ vp,
                                const float* __restrict__ qp,
                                __nv_bfloat16* __restrict__ hi, __nv_bfloat16* __restrict__ lo,
                                float* __restrict__ qloc, float* __restrict__ kloc)
{
    const int blk = blockIdx.x;
    const int tid = threadIdx.x;
    if (blk < 3072) {
        const int i = blk * 256 + tid;
        const float v = kp[i] + vp[i];
        const __nv_bfloat16 h = __float2bfloat16(v);
        hi[i] = h;
        lo[i] = __float2bfloat16(v - __bfloat162float(h));
    } else {
        const int bp = blk - 3072;
        const float* qb = qp + (long)bp * LBLK * Cc + tid;
        const float* kb = kp + (long)bp * LBLK * Cc + tid;
        float sq = 0.f, sk = 0.f;
        for (int i = 0; i < LBLK; i++) { sq += qb[i * Cc]; sk += kb[i * Cc]; }
        qloc[bp * Cc + tid] = sq * (1.f / (float)LBLK);
        kloc[bp * Cc + tid] = sk * (1.f / (float)LBLK);
    }
}

// ---------------- attention with inline routing (r10-proven) ----------------
#define KCHUNK 128
__global__ void attention_kernel(const float* __restrict__ q2,
                                 const float* __restrict__ k2,
                                 const float* __restrict__ v2,
                                 const float* __restrict__ qloc,
                                 const float* __restrict__ kloc,
                                 __nv_bfloat16* __restrict__ ctx_hi,
                                 __nv_bfloat16* __restrict__ ctx_lo)
{
    __shared__ float Ks[KCHUNK * DK];
    __shared__ float Vs[KCHUNK * DK];
    __shared__ float Sl[8];
    __shared__ int   Rs[KV];

    const int blk = blockIdx.x;
    const int h = blk % NHh;
    const int p = (blk / NHh) % Pp;
    const int b = blk / (NHh * Pp);
    const int tid = threadIdx.x;
    const int wid = tid >> 5;
    const int lane = tid & 31;

    {
        const float* q = qloc + (b * Pp + p) * Cc;
        const float* k = kloc + (b * Pp + wid) * Cc;
        float partial = 0.f;
#pragma unroll
        for (int c = lane; c < Cc; c += 32) partial += q[c] * k[c];
#pragma unroll
        for (int o = 16; o; o >>= 1) partial += __shfl_xor_sync(0xffffffff, partial, o);
        if (lane == 0) Sl[wid] = partial;
        __syncthreads();
        if (tid == 0) {
            bool used[8] = {};
            for (int t = 0; t < KV; t++) {
                int best = 0; float bv = -1e30f;
                for (int j = 0; j < Pp; j++)
                    if (!used[j] && Sl[j] > bv) { bv = Sl[j]; best = j; }
                used[best] = true;
                Rs[t] = best;
            }
        }
    }

    const bool active = (tid < LBLK);
    unsigned long long qv2[DK / 2], acc2[DK / 2];
    float m = -1e30f, l = 0.f;
    if (active) {
        const float* qrow = q2 + ((long)((b * Pp + p) * LBLK + tid)) * Cc + h * DK;
#pragma unroll
        for (int d2 = 0; d2 < DK / 2; d2++) {
            qv2[d2] = pk2(qrow[2 * d2] * QK_SCALE, qrow[2 * d2 + 1] * QK_SCALE);
            acc2[d2] = 0ull;
        }
    }

    for (int ch = 0; ch < LKEY / KCHUNK; ch++) {
        __syncthreads();
        const int kg0 = ch * KCHUNK;
        for (int i = tid; i < KCHUNK * (DK / 4); i += blockDim.x) {
            const int row = i >> 3;
            const int d4  = (i & 7) * 4;
            const int kg  = kg0 + row;
            const int ks  = kg / LBLK;
            const int rr  = kg - ks * LBLK;
            const int r   = Rs[ks];
            const long base = ((long)(b * Pp + r) * LBLK + rr) * Cc + h * DK + d4;
            *(float4*)&Ks[row * DK + d4] = *(const float4*)&k2[base];
            *(float4*)&Vs[row * DK + d4] = *(const float4*)&v2[base];
        }
        __syncthreads();
        if (active) {
            for (int k = 0; k < KCHUNK; k++) {
                const unsigned long long* kr = (const unsigned long long*)&Ks[k * DK];
                unsigned long long s0 = 0ull, s1 = 0ull, s2 = 0ull, s3 = 0ull;
#pragma unroll
                for (int d2 = 0; d2 < DK / 2; d2 += 4) {
                    s0 = ffma2(qv2[d2 + 0], kr[d2 + 0], s0);
                    s1 = ffma2(qv2[d2 + 1], kr[d2 + 1], s1);
                    s2 = ffma2(qv2[d2 + 2], kr[d2 + 2], s2);
                    s3 = ffma2(qv2[d2 + 3], kr[d2 + 3], s3);
                }
                const float2 f0 = upk2(s0), f1 = upk2(s1), f2 = upk2(s2), f3 = upk2(s3);
                const float s = ((f0.x + f0.y) + (f1.x + f1.y)) + ((f2.x + f2.y) + (f3.x + f3.y));
                const float mnew = fmaxf(m, s);
                const float corr = ex2f(m - mnew);
                const float pe   = ex2f(s - mnew);
                l = fmaf(l, corr, pe);
                const unsigned long long cc = pk2(corr, corr);
                const unsigned long long pp = pk2(pe, pe);
                const unsigned long long* vr = (const unsigned long long*)&Vs[k * DK];
#pragma unroll
                for (int d2 = 0; d2 < DK / 2; d2++)
                    acc2[d2] = ffma2(acc2[d2], cc, fmul2(pp, vr[d2]));
                m = mnew;
            }
        }
    }

    if (active) {
        const float inv = 1.0f / l;
        const long base = ((long)((b * Pp + p) * LBLK + tid)) * Cc + h * DK;
#pragma unroll
        for (int d2 = 0; d2 < DK / 2; d2++) {
            float2 f = upk2(acc2[d2]);
            const float v0 = f.x * inv, v1 = f.y * inv;
            const __nv_bfloat16 h0 = __float2bfloat16(v0);
            const __nv_bfloat16 h1 = __float2bfloat16(v1);
            *(__nv_bfloat162*)&ctx_hi[base + 2 * d2] = __nv_bfloat162(h0, h1);
            *(__nv_bfloat162*)&ctx_lo[base + 2 * d2] = __nv_bfloat162(
                __float2bfloat16(v0 - __bfloat162float(h0)),
                __float2bfloat16(v1 - __bfloat162float(h1)));
        }
    }
}

// ---------------- fused residual add + LayerNorm ----------------
__global__ void add_ln_kernel(const float* __restrict__ a, const float* __restrict__ bsrc,
                              const float* __restrict__ g, const float* __restrict__ beta,
                              float* __restrict__ out)
{
    const int mrow = blockIdx.x;
    const int c = threadIdx.x;
    __shared__ float red[Cc];
    const float v = a[(long)mrow * Cc + c] + bsrc[(long)mrow * Cc + c];
    red[c] = v;
    __syncthreads();
    for (int s = Cc / 2; s > 0; s >>= 1) {
        if (c < s) red[c] += red[c + s];
        __syncthreads();
    }
    const float mean = red[0] * (1.f / (float)Cc);
    __syncthreads();
    const float d = v - mean;
    red[c] = d * d;
    __syncthreads();
    for (int s = Cc / 2; s > 0; s >>= 1) {
        if (c < s) red[c] += red[c + s];
        __syncthreads();
    }
    const float var = red[0] * (1.f / (float)Cc);
    out[(long)mrow * Cc + c] = d * rsqrtf(var + 1e-5f) * g[c] + beta[c];
}

__global__ void add_lnK_kernel(const float* __restrict__ a, const float* __restrict__ pbase,
                               const float* __restrict__ cb,
                               const float* __restrict__ g, const float* __restrict__ beta,
                               float* __restrict__ out)
{
    const int mrow = blockIdx.x;
    const int c = threadIdx.x;
    __shared__ float red[Cc];
    const long off = (long)mrow * Cc + c;
    float v = a[off] + cb[c];
#pragma unroll
    for (int s = 0; s < NSPLIT; s++) v += pbase[off + (size_t)s * NELEM];
    red[c] = v;
    __syncthreads();
    for (int s = Cc / 2; s > 0; s >>= 1) {
        if (c < s) red[c] += red[c + s];
        __syncthreads();
    }
    const float mean = red[0] * (1.f / (float)Cc);
    __syncthreads();
    const float d = v - mean;
    red[c] = d * d;
    __syncthreads();
    for (int s = Cc / 2; s > 0; s >>= 1) {
        if (c < s) red[c] += red[c + s];
        __syncthreads();
    }
    const float var = red[0] * (1.f / (float)Cc);
    out[off] = d * rsqrtf(var + 1e-5f) * g[c] + beta[c];
}

// ---------------- launcher (single stream, r13-proven best) ----------------
extern "C" void kernel_launch(void* const* d_in, const int* in_sizes, int n_in,
                              void* d_out, int out_size)
{
    const float* x        = (const float*)d_in[0];
    const float* wq_proj  = (const float*)d_in[1];
    const float* bq_proj  = (const float*)d_in[2];
    const float* wk_proj  = (const float*)d_in[3];
    const float* bk_proj  = (const float*)d_in[4];
    const float* wv_proj  = (const float*)d_in[5];
    const float* bv_proj  = (const float*)d_in[6];
    const float* wq_a     = (const float*)d_in[7];
    const float* bq_a     = (const float*)d_in[8];
    const float* wk_a     = (const float*)d_in[9];
    const float* bk_a     = (const float*)d_in[10];
    const float* wv_a     = (const float*)d_in[11];
    const float* bv_a     = (const float*)d_in[12];
    const float* wo_a     = (const float*)d_in[13];
    const float* bo_a     = (const float*)d_in[14];
    const float* conv_w   = (const float*)d_in[15];
    const float* conv_b   = (const float*)d_in[16];
    const float* ln1_g    = (const float*)d_in[17];
    const float* ln1_b    = (const float*)d_in[18];
    const float* ln2_g    = (const float*)d_in[19];
    const float* ln2_b    = (const float*)d_in[20];
    float* out = (float*)d_out;

    float* buf = nullptr;   cudaGetSymbolAddress((void**)&buf, g_buf);
    float* loc = nullptr;   cudaGetSymbolAddress((void**)&loc, g_loc);
    __nv_bfloat16 *xh, *xl, *ah, *al, *cxh, *cxl, *kvh, *kvl, *wth, *wtl, *w7h, *w7l;
    cudaGetSymbolAddress((void**)&xh,  g_x_hi);
    cudaGetSymbolAddress((void**)&xl,  g_x_lo);
    cudaGetSymbolAddress((void**)&ah,  g_act_hi);
    cudaGetSymbolAddress((void**)&al,  g_act_lo);
    cudaGetSymbolAddress((void**)&cxh, g_ctx_hi);
    cudaGetSymbolAddress((void**)&cxl, g_ctx_lo);
    cudaGetSymbolAddress((void**)&kvh, g_kvg_hi);
    cudaGetSymbolAddress((void**)&kvl, g_kvg_lo);
    cudaGetSymbolAddress((void**)&wth, g_wt_hi);
    cudaGetSymbolAddress((void**)&wtl, g_wt_lo);
    cudaGetSymbolAddress((void**)&w7h, g_w7_hi);
    cudaGetSymbolAddress((void**)&w7l, g_w7_lo);

    float* qp   = buf + 0l * NELEM;
    float* kp   = buf + 1l * NELEM;
    float* vp   = buf + 2l * NELEM;
    float* xres = buf + 3l * NELEM;
    float* q2   = buf + 4l * NELEM;
    float* k2   = buf + 5l * NELEM;
    float* v2   = buf + 6l * NELEM;
    float* rout = buf + 7l * NELEM;
    float* cnvp = buf + 8l * NELEM;
    float* qloc = loc;
    float* kloc = loc + 16 * Cc;

    // 1: all decomposition (w7 + conv weight + x) in one tight launch (2816 CTAs)
    {
        DecompArgs da;
        da.w[0] = wq_proj; da.w[1] = wk_proj; da.w[2] = wv_proj;
        da.w[3] = wq_a;    da.w[4] = wk_a;    da.w[5] = wv_a;    da.w[6] = wo_a;
        da.convw = conv_w; da.x = x;
        decomp_merged_kernel<<<2816, 256>>>(da);
    }

    // 2: q/k/v block projections
    {
        GemmSetT gs;
        for (int i = 0; i < 3; i++) {
            gs.Ah[i] = xh; gs.Al[i] = xl;
            gs.Bh[i] = w7h + i * WSZ; gs.Bl[i] = w7l + i * WSZ;
            gs.Ch[i] = ah + (long)i * NELEM; gs.Cl[i] = al + (long)i * NELEM;
        }
        gs.bias[0] = bq_proj; gs.bias[1] = bk_proj; gs.bias[2] = bv_proj;
        gs.C[0] = qp; gs.C[1] = kp; gs.C[2] = vp;
        gemm_mma_kernel<<<dim3(NROW / 128, Cc / 128, 3), 256>>>(gs);
    }

    // 3: kvg decompose + pool (3088 CTAs, tight)
    kvg_pool_kernel<<<3072 + 16, 256>>>(kp, vp, qp, kvh, kvl, qloc, kloc);

    // 4: conv via reg-pipelined mma.sync
    conv_mma_kernel<<<dim3(NROW / 128, Cc / 128, NSPLIT), 256>>>(kvh, kvl, wth, wtl, cnvp);

    // 5: attention head projections
    {
        GemmSetT gs;
        for (int i = 0; i < 3; i++) {
            gs.Ah[i] = ah + (long)i * NELEM; gs.Al[i] = al + (long)i * NELEM;
            gs.Bh[i] = w7h + (3 + i) * WSZ;  gs.Bl[i] = w7l + (3 + i) * WSZ;
            gs.Ch[i] = nullptr; gs.Cl[i] = nullptr;
        }
        gs.bias[0] = bq_a; gs.bias[1] = bk_a; gs.bias[2] = bv_a;
        gs.C[0] = q2; gs.C[1] = k2; gs.C[2] = v2;
        gemm_mma_kernel<<<dim3(NROW / 128, Cc / 128, 3), 256>>>(gs);
    }

    // 6: routed attention (routing inline; emits ctx hi/lo)
    attention_kernel<<<Bsz * Pp * NHh, 256>>>(q2, k2, v2, qloc, kloc, cxh, cxl);

    // 7: output projection
    {
        GemmSetT gs;
        gs.Ah[0] = cxh; gs.Al[0] = cxl;
        gs.Bh[0] = w7h + 6 * WSZ; gs.Bl[0] = w7l + 6 * WSZ;
        gs.bias[0] = bo_a;
        gs.C[0] = rout;
        gs.Ch[0] = nullptr; gs.Cl[0] = nullptr;
        for (int i = 1; i < 3; i++) {
            gs.Ah[i] = cxh; gs.Al[i] = cxl;
            gs.Bh[i] = w7h; gs.Bl[i] = w7l;
            gs.bias[i] = bo_a; gs.C[i] = rout;
            gs.Ch[i] = nullptr; gs.Cl[i] = nullptr;
        }
        gemm_mma_kernel<<<dim3(NROW / 128, Cc / 128, 1), 256>>>(gs);
    }

    // 8-9: LayerNorms
    add_ln_kernel<<<NROW, Cc>>>(x, rout, ln1_g, ln1_b, xres);
    add_lnK_kernel<<<NROW, Cc>>>(xres, cnvp, conv_b, ln2_g, ln2_b, out);
}

// round 16
// speedup vs baseline: 1.6965x; 1.0957x over previous
#include <cuda_runtime.h>
#include <cuda_bf16.h>
#include <math.h>
#include <stdint.h>

// Problem constants
#define Bsz 2
#define Hh  64
#define Ww  24
#define Cc  256
#define Pp  8
#define HP  8
#define NHh 8
#define DK  32
#define KV  4
#define NROW (Bsz*Hh*Ww)       // 3072
#define NELEM (NROW*Cc)        // 786432
#define LBLK (HP*Ww)           // 192
#define LKEY (KV*LBLK)         // 768
#define KTOT (25*Cc)           // 6400 conv K
#define NSPLIT 3
#define NCHUNK 200             // 6400 / 32
#define WSZ ((long)Cc*Cc)

#define QK_SCALE (0.17677669529663687f * 1.44269504088896340f)

// ---------------- device scratch ----------------
// fp32 slots: 0:qp 1:kp 2:vp 3:xres 4:q2 5:k2 6:v2 7:rout 8..10:conv partials
__device__ float g_buf[11u * NELEM];
__device__ float g_loc[2 * 16 * Cc];
__device__ __nv_bfloat16 g_x_hi[NELEM],   g_x_lo[NELEM];
__device__ __nv_bfloat16 g_act_hi[3u*NELEM], g_act_lo[3u*NELEM];
__device__ __nv_bfloat16 g_ctx_hi[NELEM], g_ctx_lo[NELEM];
__device__ __nv_bfloat16 g_kvg_hi[NELEM], g_kvg_lo[NELEM];
__device__ __nv_bfloat16 g_wt_hi[Cc * KTOT], g_wt_lo[Cc * KTOT];
__device__ __nv_bfloat16 g_w7_hi[7u*Cc*Cc], g_w7_lo[7u*Cc*Cc];

// ---------------- packed f32x2 helpers ----------------
__device__ __forceinline__ unsigned long long pk2(float lo, float hi) {
    unsigned long long r;
    asm("mov.b64 %0, {%1, %2};" : "=l"(r)
        : "r"(__float_as_uint(lo)), "r"(__float_as_uint(hi)));
    return r;
}
__device__ __forceinline__ unsigned long long ffma2(unsigned long long a,
                                                    unsigned long long b,
                                                    unsigned long long c) {
    unsigned long long d;
    asm("fma.rn.f32x2 %0, %1, %2, %3;" : "=l"(d) : "l"(a), "l"(b), "l"(c));
    return d;
}
__device__ __forceinline__ unsigned long long fadd2(unsigned long long a,
                                                    unsigned long long b) {
    unsigned long long d;
    asm("add.rn.f32x2 %0, %1, %2;" : "=l"(d) : "l"(a), "l"(b));
    return d;
}
__device__ __forceinline__ float2 upk2(unsigned long long v) {
    unsigned int lo, hi;
    asm("mov.b64 {%0, %1}, %2;" : "=r"(lo), "=r"(hi) : "l"(v));
    return make_float2(__uint_as_float(lo), __uint_as_float(hi));
}
__device__ __forceinline__ float ex2f(float x) {
    float r;
    asm("ex2.approx.ftz.f32 %0, %1;" : "=f"(r) : "f"(x));
    return r;
}

// ---------------- warp MMA helpers ----------------
__device__ __forceinline__ uint32_t smem_u32(const void* p) {
    uint32_t a;
    asm("{ .reg .u64 t; cvta.to.shared.u64 t, %1; cvt.u32.u64 %0, t; }"
        : "=r"(a) : "l"(p));
    return a;
}
#define SWZ64(o) ((o) ^ (((o) >> 3) & 0x30))

__device__ __forceinline__ void ldsm4(uint32_t* r, uint32_t addr) {
    asm volatile("ldmatrix.sync.aligned.m8n8.x4.shared.b16 {%0,%1,%2,%3}, [%4];"
                 : "=r"(r[0]), "=r"(r[1]), "=r"(r[2]), "=r"(r[3]) : "r"(addr));
}
__device__ __forceinline__ void mma_bf16(float* c, const uint32_t* a, const uint32_t* b) {
    asm volatile(
        "mma.sync.aligned.m16n8k16.row.col.f32.bf16.bf16.f32 "
        "{%0,%1,%2,%3}, {%4,%5,%6,%7}, {%8,%9}, {%0,%1,%2,%3};"
        : "+f"(c[0]), "+f"(c[1]), "+f"(c[2]), "+f"(c[3])
        : "r"(a[0]), "r"(a[1]), "r"(a[2]), "r"(a[3]), "r"(b[0]), "r"(b[1]));
}

// ================= tensor-core projection GEMM (hi/lo split), r5/r10-proven ===========
struct GemmSetT {
    const __nv_bfloat16 *Ah[3], *Al[3], *Bh[3], *Bl[3];
    const float* bias[3];
    float* C[3];
    __nv_bfloat16 *Ch[3], *Cl[3];   // optional (null => skip)
};

__global__ __launch_bounds__(256, 1)
void gemm_mma_kernel(GemmSetT gs)
{
    __shared__ char smem[32768];
    const uint32_t sb = smem_u32(smem);
    const uint32_t A_HI = sb, A_LO = sb + 8192, B_HI = sb + 16384, B_LO = sb + 24576;

    const int z = blockIdx.z;
    const __nv_bfloat16* __restrict__ Ah = gs.Ah[z];
    const __nv_bfloat16* __restrict__ Al = gs.Al[z];
    const __nv_bfloat16* __restrict__ Bh = gs.Bh[z];
    const __nv_bfloat16* __restrict__ Bl = gs.Bl[z];
    const float* __restrict__ bias = gs.bias[z];
    float* __restrict__ C = gs.C[z];
    __nv_bfloat16* __restrict__ Ch = gs.Ch[z];
    __nv_bfloat16* __restrict__ Cl = gs.Cl[z];

    const int tid  = threadIdx.x;
    const int wid  = tid >> 5;
    const int lane = tid & 31;
    const int m0 = blockIdx.x * 128;
    const int n0 = blockIdx.y * 128;
    const int wm = wid & 3;
    const int wn = wid >> 2;

    int l_row[2], l_seg[2];
#pragma unroll
    for (int i = 0; i < 2; i++) {
        const int idx = tid + 256 * i;
        l_row[i] = idx >> 2;
        l_seg[i] = idx & 3;
    }

    float acc[2][8][4];
#pragma unroll
    for (int i = 0; i < 2; i++)
#pragma unroll
        for (int j = 0; j < 8; j++)
#pragma unroll
            for (int q = 0; q < 4; q++) acc[i][j][q] = 0.f;

    uint4 rAh[2], rAl[2], rBh[2], rBl[2];
#pragma unroll
    for (int i = 0; i < 2; i++) {
        const long aoff = (long)(m0 + l_row[i]) * Cc + l_seg[i] * 8;
        rAh[i] = *(const uint4*)(Ah + aoff);
        rAl[i] = *(const uint4*)(Al + aoff);
        const long boff = (long)(n0 + l_row[i]) * Cc + l_seg[i] * 8;
        rBh[i] = *(const uint4*)(Bh + boff);
        rBl[i] = *(const uint4*)(Bl + boff);
    }

    for (int c = 0; c < 8; c++) {
        __syncthreads();
#pragma unroll
        for (int i = 0; i < 2; i++) {
            const uint32_t so = SWZ64((uint32_t)(l_row[i] * 64 + l_seg[i] * 16));
            *(uint4*)(smem + so)         = rAh[i];
            *(uint4*)(smem + 8192 + so)  = rAl[i];
            *(uint4*)(smem + 16384 + so) = rBh[i];
            *(uint4*)(smem + 24576 + so) = rBl[i];
        }
        __syncthreads();

        if (c + 1 < 8) {
            const int kb = (c + 1) * 32;
#pragma unroll
            for (int i = 0; i < 2; i++) {
                const long aoff = (long)(m0 + l_row[i]) * Cc + kb + l_seg[i] * 8;
                rAh[i] = *(const uint4*)(Ah + aoff);
                rAl[i] = *(const uint4*)(Al + aoff);
                const long boff = (long)(n0 + l_row[i]) * Cc + kb + l_seg[i] * 8;
                rBh[i] = *(const uint4*)(Bh + boff);
                rBl[i] = *(const uint4*)(Bl + boff);
            }
        }

#pragma unroll
        for (int kst = 0; kst < 2; kst++) {
            uint32_t ahi[2][4], alo[2][4];
#pragma unroll
            for (int mh = 0; mh < 2; mh++) {
                const int tile = lane >> 3;
                const int row = wm * 32 + mh * 16 + ((tile & 1) << 3) + (lane & 7);
                const int unit = kst * 2 + (tile >> 1);
                const uint32_t so = SWZ64((uint32_t)(row * 64 + unit * 16));
                ldsm4(ahi[mh], A_HI + so);
                ldsm4(alo[mh], A_LO + so);
            }
            uint32_t bhi[8][2], blo[8][2];
#pragma unroll
            for (int ng = 0; ng < 4; ng++) {
                const int tile = lane >> 3;
                const int row = wn * 64 + ng * 16 + ((tile >> 1) << 3) + (lane & 7);
                const int unit = kst * 2 + (tile & 1);
                const uint32_t so = SWZ64((uint32_t)(row * 64 + unit * 16));
                uint32_t th[4], tl[4];
                ldsm4(th, B_HI + so);
                ldsm4(tl, B_LO + so);
                bhi[ng * 2][0] = th[0]; bhi[ng * 2][1] = th[1];
                bhi[ng * 2 + 1][0] = th[2]; bhi[ng * 2 + 1][1] = th[3];
                blo[ng * 2][0] = tl[0]; blo[ng * 2][1] = tl[1];
                blo[ng * 2 + 1][0] = tl[2]; blo[ng * 2 + 1][1] = tl[3];
            }
#pragma unroll
            for (int mh = 0; mh < 2; mh++)
#pragma unroll
                for (int nt = 0; nt < 8; nt++) {
                    mma_bf16(acc[mh][nt], ahi[mh], bhi[nt]);
                    mma_bf16(acc[mh][nt], alo[mh], bhi[nt]);
                    mma_bf16(acc[mh][nt], ahi[mh], blo[nt]);
                }
        }
    }

    // epilogue: bias + fp32 C + optional bf16 hi/lo decompose
#pragma unroll
    for (int mh = 0; mh < 2; mh++) {
        const int mrow = m0 + wm * 32 + mh * 16 + (lane >> 2);
#pragma unroll
        for (int nt = 0; nt < 8; nt++) {
            const int n = n0 + wn * 64 + nt * 8 + (lane & 3) * 2;
            const float2 bi = *(const float2*)&bias[n];
            const float v0 = acc[mh][nt][0] + bi.x;
            const float v1 = acc[mh][nt][1] + bi.y;
            const float v2 = acc[mh][nt][2] + bi.x;
            const float v3 = acc[mh][nt][3] + bi.y;
            const size_t o0 = (size_t)mrow * Cc + n;
            const size_t o1 = (size_t)(mrow + 8) * Cc + n;
            *(float2*)&C[o0] = make_float2(v0, v1);
            *(float2*)&C[o1] = make_float2(v2, v3);
            if (Ch) {
                const __nv_bfloat16 h0 = __float2bfloat16(v0);
                const __nv_bfloat16 h1 = __float2bfloat16(v1);
                const __nv_bfloat16 h2 = __float2bfloat16(v2);
                const __nv_bfloat16 h3 = __float2bfloat16(v3);
                *(__nv_bfloat162*)&Ch[o0] = __nv_bfloat162(h0, h1);
                *(__nv_bfloat162*)&Ch[o1] = __nv_bfloat162(h2, h3);
                *(__nv_bfloat162*)&Cl[o0] = __nv_bfloat162(
                    __float2bfloat16(v0 - __bfloat162float(h0)),
                    __float2bfloat16(v1 - __bfloat162float(h1)));
                *(__nv_bfloat162*)&Cl[o1] = __nv_bfloat162(
                    __float2bfloat16(v2 - __bfloat162float(h2)),
                    __float2bfloat16(v3 - __bfloat162float(h3)));
            }
        }
    }
}

// ---------------- conv implicit GEMM, 128x128 tile, reg-pipelined K32 (r5/r10-proven) ------
__global__ __launch_bounds__(256, 1)
void conv_mma_kernel(const __nv_bfloat16* __restrict__ a_hi,
                     const __nv_bfloat16* __restrict__ a_lo,
                     const __nv_bfloat16* __restrict__ b_hi,
                     const __nv_bfloat16* __restrict__ b_lo,
                     float* __restrict__ part)
{
    __shared__ char smem[32768];
    const uint32_t sb = smem_u32(smem);
    const uint32_t A_HI = sb, A_LO = sb + 8192, B_HI = sb + 16384, B_LO = sb + 24576;

    const int tid  = threadIdx.x;
    const int wid  = tid >> 5;
    const int lane = tid & 31;
    const int m0 = blockIdx.x * 128;
    const int n0 = blockIdx.y * 128;
    const int z  = blockIdx.z;
    const int cbeg = (z * NCHUNK) / 3;
    const int cend = ((z + 1) * NCHUNK) / 3;

    const int wm = wid & 3;
    const int wn = wid >> 2;

    int a_row[2], a_seg[2], a_h[2], a_w[2];
    long a_base[2];
    int b_rw[2], b_sg[2];
#pragma unroll
    for (int i = 0; i < 2; i++) {
        const int idx = tid + 256 * i;
        a_row[i] = idx >> 2;
        a_seg[i] = idx & 3;
        const int m = m0 + a_row[i];
        const int b = m / (Hh * Ww);
        a_h[i] = (m / Ww) % Hh;
        a_w[i] = m % Ww;
        a_base[i] = (long)b * Hh * Ww * Cc;
        b_rw[i] = idx >> 2;
        b_sg[i] = idx & 3;
    }

    float acc[2][8][4];
#pragma unroll
    for (int i = 0; i < 2; i++)
#pragma unroll
        for (int j = 0; j < 8; j++)
#pragma unroll
            for (int q = 0; q < 4; q++) acc[i][j][q] = 0.f;

    uint4 rAh[2], rAl[2], rBh[2], rBl[2];
    {
        const int kb = cbeg * 32;
        const int patch = kb >> 8;
        const int kh = patch / 5, kw = patch % 5;
        const int ci0 = kb & 255;
#pragma unroll
        for (int i = 0; i < 2; i++) {
            const int hh = a_h[i] + kh - 2;
            const int ww = a_w[i] + kw - 2;
            if (hh >= 0 && hh < Hh && ww >= 0 && ww < Ww) {
                const long off = a_base[i] + ((long)hh * Ww + ww) * Cc + ci0 + a_seg[i] * 8;
                rAh[i] = *(const uint4*)(a_hi + off);
                rAl[i] = *(const uint4*)(a_lo + off);
            } else {
                rAh[i] = make_uint4(0, 0, 0, 0);
                rAl[i] = make_uint4(0, 0, 0, 0);
            }
            const long boff = (long)(n0 + b_rw[i]) * KTOT + kb + b_sg[i] * 8;
            rBh[i] = *(const uint4*)(b_hi + boff);
            rBl[i] = *(const uint4*)(b_lo + boff);
        }
    }

    for (int c = cbeg; c < cend; c++) {
        __syncthreads();
#pragma unroll
        for (int i = 0; i < 2; i++) {
            const uint32_t soA = SWZ64((uint32_t)(a_row[i] * 64 + a_seg[i] * 16));
            *(uint4*)(smem + soA)        = rAh[i];
            *(uint4*)(smem + 8192 + soA) = rAl[i];
            const uint32_t soB = SWZ64((uint32_t)(b_rw[i] * 64 + b_sg[i] * 16));
            *(uint4*)(smem + 16384 + soB) = rBh[i];
            *(uint4*)(smem + 24576 + soB) = rBl[i];
        }
        __syncthreads();

        if (c + 1 < cend) {
            const int kb = (c + 1) * 32;
            const int patch = kb >> 8;
            const int kh = patch / 5, kw = patch % 5;
            const int ci0 = kb & 255;
#pragma unroll
            for (int i = 0; i < 2; i++) {
                const int hh = a_h[i] + kh - 2;
                const int ww = a_w[i] + kw - 2;
                if (hh >= 0 && hh < Hh && ww >= 0 && ww < Ww) {
                    const long off = a_base[i] + ((long)hh * Ww + ww) * Cc + ci0 + a_seg[i] * 8;
                    rAh[i] = *(const uint4*)(a_hi + off);
                    rAl[i] = *(const uint4*)(a_lo + off);
                } else {
                    rAh[i] = make_uint4(0, 0, 0, 0);
                    rAl[i] = make_uint4(0, 0, 0, 0);
                }
                const long boff = (long)(n0 + b_rw[i]) * KTOT + kb + b_sg[i] * 8;
                rBh[i] = *(const uint4*)(b_hi + boff);
                rBl[i] = *(const uint4*)(b_lo + boff);
            }
        }

#pragma unroll
        for (int kst = 0; kst < 2; kst++) {
            uint32_t ahi[2][4], alo[2][4];
#pragma unroll
            for (int mh = 0; mh < 2; mh++) {
                const int tile = lane >> 3;
                const int row = wm * 32 + mh * 16 + ((tile & 1) << 3) + (lane & 7);
                const int unit = kst * 2 + (tile >> 1);
                const uint32_t so = SWZ64((uint32_t)(row * 64 + unit * 16));
                ldsm4(ahi[mh], A_HI + so);
                ldsm4(alo[mh], A_LO + so);
            }
            uint32_t bhi[8][2], blo[8][2];
#pragma unroll
            for (int ng = 0; ng < 4; ng++) {
                const int tile = lane >> 3;
                const int row = wn * 64 + ng * 16 + ((tile >> 1) << 3) + (lane & 7);
                const int unit = kst * 2 + (tile & 1);
                const uint32_t so = SWZ64((uint32_t)(row * 64 + unit * 16));
                uint32_t th[4], tl[4];
                ldsm4(th, B_HI + so);
                ldsm4(tl, B_LO + so);
                bhi[ng * 2][0] = th[0]; bhi[ng * 2][1] = th[1];
                bhi[ng * 2 + 1][0] = th[2]; bhi[ng * 2 + 1][1] = th[3];
                blo[ng * 2][0] = tl[0]; blo[ng * 2][1] = tl[1];
                blo[ng * 2 + 1][0] = tl[2]; blo[ng * 2 + 1][1] = tl[3];
            }
#pragma unroll
            for (int mh = 0; mh < 2; mh++)
#pragma unroll
                for (int nt = 0; nt < 8; nt++) {
                    mma_bf16(acc[mh][nt], ahi[mh], bhi[nt]);
                    mma_bf16(acc[mh][nt], alo[mh], bhi[nt]);
                    mma_bf16(acc[mh][nt], ahi[mh], blo[nt]);
                }
        }
    }

    float* base = part + (size_t)z * NELEM;
#pragma unroll
    for (int mh = 0; mh < 2; mh++) {
        const int mrow = m0 + wm * 32 + mh * 16 + (lane >> 2);
#pragma unroll
        for (int nt = 0; nt < 8; nt++) {
            const int n = n0 + wn * 64 + nt * 8 + (lane & 3) * 2;
            *(float2*)&base[(size_t)mrow * Cc + n] =
                make_float2(acc[mh][nt][0], acc[mh][nt][1]);
            *(float2*)&base[(size_t)(mrow + 8) * Cc + n] =
                make_float2(acc[mh][nt][2], acc[mh][nt][3]);
        }
    }
}

// ---------------- merged decompose: w7 (448) + conv weight (1600) + x (768) ----------------
struct DecompArgs {
    const float* w[7];
    const float* convw;
    const float* x;
};

__global__ void decomp_merged_kernel(DecompArgs da)
{
    const int blk = blockIdx.x;
    const int tid = threadIdx.x;
    const int tx = tid & 31, ty = tid >> 5;

    if (blk < 448) {
        const int z = blk >> 6;
        const int rem = blk & 63;
        const int k0 = (rem & 7) * 32;
        const int n0 = (rem >> 3) * 32;
        const float* __restrict__ w = da.w[z];
        const long zo = (long)z * WSZ;
        __shared__ float tile[32][33];
#pragma unroll
        for (int i = 0; i < 4; i++)
            tile[ty + i * 8][tx] = w[(long)(k0 + ty + i * 8) * Cc + n0 + tx];
        __syncthreads();
#pragma unroll
        for (int i = 0; i < 4; i++) {
            const float v = tile[tx][ty + i * 8];
            const __nv_bfloat16 h = __float2bfloat16(v);
            const long o = zo + (long)(n0 + ty + i * 8) * Cc + k0 + tx;
            g_w7_hi[o] = h;
            g_w7_lo[o] = __float2bfloat16(v - __bfloat162float(h));
        }
    } else if (blk < 2048) {
        const int i2 = blk - 448;
        const int k0 = (i2 % 200) * 32;
        const int n0 = (i2 / 200) * 32;
        __shared__ float tile[32][33];
#pragma unroll
        for (int i = 0; i < 4; i++)
            tile[ty + i * 8][tx] = da.convw[(long)(k0 + ty + i * 8) * Cc + n0 + tx];
        __syncthreads();
#pragma unroll
        for (int i = 0; i < 4; i++) {
            const float v = tile[tx][ty + i * 8];
            const __nv_bfloat16 h = __float2bfloat16(v);
            const long o = (long)(n0 + ty + i * 8) * KTOT + k0 + tx;
            g_wt_hi[o] = h;
            g_wt_lo[o] = __float2bfloat16(v - __bfloat162float(h));
        }
    } else {
        const int idx = (blk - 2048) * 256 + tid;
        if (idx < NELEM / 4) {
            const float4 v = ((const float4*)da.x)[idx];
            const __nv_bfloat16 h0 = __float2bfloat16(v.x), h1 = __float2bfloat16(v.y);
            const __nv_bfloat16 h2 = __float2bfloat16(v.z), h3 = __float2bfloat16(v.w);
            ((__nv_bfloat162*)g_x_hi)[idx * 2]     = __nv_bfloat162(h0, h1);
            ((__nv_bfloat162*)g_x_hi)[idx * 2 + 1] = __nv_bfloat162(h2, h3);
            ((__nv_bfloat162*)g_x_lo)[idx * 2]     = __nv_bfloat162(
                __float2bfloat16(v.x - __bfloat162float(h0)),
                __float2bfloat16(v.y - __bfloat162float(h1)));
            ((__nv_bfloat162*)g_x_lo)[idx * 2 + 1] = __nv_bfloat162(
                __float2bfloat16(v.z - __bfloat162float(h2)),
                __float2bfloat16(v.w - __bfloat162float(h3)));
        }
    }
}

// ---------------- merged: decompose kvg = kp+vp (3072 CTAs) + pool (16 CTAs) ----------------
__global__ void kvg_pool_kernel(const float* __restrict__ kp, const float* __restrict__ vp,
                                const float* __restrict__ qp,
                                __nv_bfloat16* __restrict__ hi, __nv_bfloat16* __restrict__ lo,
                                float* __restrict__ qloc, float* __restrict__ kloc)
{
    const int blk = blockIdx.x;
    const int tid = threadIdx.x;
    if (blk < 3072) {
        const int i = blk * 256 + tid;
        const float v = kp[i] + vp[i];
        const __nv_bfloat16 h = __float2bfloat16(v);
        hi[i] = h;
        lo[i] = __float2bfloat16(v - __bfloat162float(h));
    } else {
        const int bp = blk - 3072;
        const float* qb = qp + (long)bp * LBLK * Cc + tid;
        const float* kb = kp + (long)bp * LBLK * Cc + tid;
        float sq = 0.f, sk = 0.f;
        for (int i = 0; i < LBLK; i++) { sq += qb[i * Cc]; sk += kb[i * Cc]; }
        qloc[bp * Cc + tid] = sq * (1.f / (float)LBLK);
        kloc[bp * Cc + tid] = sk * (1.f / (float)LBLK);
    }
}

// ---------------- attention: inline routing + fixed-reference softmax ----------------
// Softmax shifted by M = s_0 (score vs first routed key) instead of a running max.
// Shift-invariance makes this exact; key0's contribution is exp2(0)=1 so l >= 1.
// Removes per-key fmaxf / corr-ex2 / accumulator rescale / fmul2 (warp-uniform, no divergence).
#define KCHUNK 128
__global__ void attention_kernel(const float* __restrict__ q2,
                                 const float* __restrict__ k2,
                                 const float* __restrict__ v2,
                                 const float* __restrict__ qloc,
                                 const float* __restrict__ kloc,
                                 __nv_bfloat16* __restrict__ ctx_hi,
                                 __nv_bfloat16* __restrict__ ctx_lo)
{
    __shared__ float Ks[KCHUNK * DK];
    __shared__ float Vs[KCHUNK * DK];
    __shared__ float Sl[8];
    __shared__ float K0[DK];
    __shared__ int   Rs[KV];

    const int blk = blockIdx.x;
    const int h = blk % NHh;
    const int p = (blk / NHh) % Pp;
    const int b = blk / (NHh * Pp);
    const int tid = threadIdx.x;
    const int wid = tid >> 5;
    const int lane = tid & 31;

    // inline routing
    {
        const float* q = qloc + (b * Pp + p) * Cc;
        const float* k = kloc + (b * Pp + wid) * Cc;
        float partial = 0.f;
#pragma unroll
        for (int c = lane; c < Cc; c += 32) partial += q[c] * k[c];
#pragma unroll
        for (int o = 16; o; o >>= 1) partial += __shfl_xor_sync(0xffffffff, partial, o);
        if (lane == 0) Sl[wid] = partial;
        __syncthreads();
        if (tid == 0) {
            bool used[8] = {};
            for (int t = 0; t < KV; t++) {
                int best = 0; float bv = -1e30f;
                for (int j = 0; j < Pp; j++)
                    if (!used[j] && Sl[j] > bv) { bv = Sl[j]; best = j; }
                used[best] = true;
                Rs[t] = best;
            }
        }
    }
    __syncthreads();

    // stage key0's K row (first gathered key) for the reference score
    if (tid < DK) {
        const long k0base = ((long)((b * Pp + Rs[0]) * LBLK)) * Cc + h * DK;
        K0[tid] = k2[k0base + tid];
    }

    const bool active = (tid < LBLK);
    unsigned long long qv2[DK / 2], acc2[DK / 2];
    float M = 0.f, l = 0.f;
    if (active) {
        const float* qrow = q2 + ((long)((b * Pp + p) * LBLK + tid)) * Cc + h * DK;
#pragma unroll
        for (int d2 = 0; d2 < DK / 2; d2++) {
            qv2[d2] = pk2(qrow[2 * d2] * QK_SCALE, qrow[2 * d2 + 1] * QK_SCALE);
            acc2[d2] = 0ull;
        }
    }
    __syncthreads();
    if (active) {
        // M = s_0 = q . k0 (packed dot)
        const unsigned long long* k0p = (const unsigned long long*)K0;
        unsigned long long s0 = 0ull, s1 = 0ull, s2 = 0ull, s3 = 0ull;
#pragma unroll
        for (int d2 = 0; d2 < DK / 2; d2 += 4) {
            s0 = ffma2(qv2[d2 + 0], k0p[d2 + 0], s0);
            s1 = ffma2(qv2[d2 + 1], k0p[d2 + 1], s1);
            s2 = ffma2(qv2[d2 + 2], k0p[d2 + 2], s2);
            s3 = ffma2(qv2[d2 + 3], k0p[d2 + 3], s3);
        }
        const unsigned long long st = fadd2(fadd2(s0, s1), fadd2(s2, s3));
        const float2 f = upk2(st);
        M = f.x + f.y;
    }

    for (int ch = 0; ch < LKEY / KCHUNK; ch++) {
        __syncthreads();
        const int kg0 = ch * KCHUNK;
        for (int i = tid; i < KCHUNK * (DK / 4); i += blockDim.x) {
            const int row = i >> 3;
            const int d4  = (i & 7) * 4;
            const int kg  = kg0 + row;
            const int ks  = kg / LBLK;
            const int rr  = kg - ks * LBLK;
            const int r   = Rs[ks];
            const long base = ((long)(b * Pp + r) * LBLK + rr) * Cc + h * DK + d4;
            *(float4*)&Ks[row * DK + d4] = *(const float4*)&k2[base];
            *(float4*)&Vs[row * DK + d4] = *(const float4*)&v2[base];
        }
        __syncthreads();
        if (active) {
            for (int k = 0; k < KCHUNK; k++) {
                const unsigned long long* kr = (const unsigned long long*)&Ks[k * DK];
                unsigned long long s0 = 0ull, s1 = 0ull, s2 = 0ull, s3 = 0ull;
#pragma unroll
                for (int d2 = 0; d2 < DK / 2; d2 += 4) {
                    s0 = ffma2(qv2[d2 + 0], kr[d2 + 0], s0);
                    s1 = ffma2(qv2[d2 + 1], kr[d2 + 1], s1);
                    s2 = ffma2(qv2[d2 + 2], kr[d2 + 2], s2);
                    s3 = ffma2(qv2[d2 + 3], kr[d2 + 3], s3);
                }
                const unsigned long long st = fadd2(fadd2(s0, s1), fadd2(s2, s3));
                const float2 f = upk2(st);
                const float s = (f.x + f.y) - M;
                const float pe = ex2f(s);
                l += pe;
                const unsigned long long pp = pk2(pe, pe);
                const unsigned long long* vr = (const unsigned long long*)&Vs[k * DK];
#pragma unroll
                for (int d2 = 0; d2 < DK / 2; d2++)
                    acc2[d2] = ffma2(pp, vr[d2], acc2[d2]);
            }
        }
    }

    if (active) {
        const float inv = 1.0f / l;
        const long base = ((long)((b * Pp + p) * LBLK + tid)) * Cc + h * DK;
#pragma unroll
        for (int d2 = 0; d2 < DK / 2; d2++) {
            float2 f = upk2(acc2[d2]);
            const float v0 = f.x * inv, v1 = f.y * inv;
            const __nv_bfloat16 h0 = __float2bfloat16(v0);
            const __nv_bfloat16 h1 = __float2bfloat16(v1);
            *(__nv_bfloat162*)&ctx_hi[base + 2 * d2] = __nv_bfloat162(h0, h1);
            *(__nv_bfloat162*)&ctx_lo[base + 2 * d2] = __nv_bfloat162(
                __float2bfloat16(v0 - __bfloat162float(h0)),
                __float2bfloat16(v1 - __bfloat162float(h1)));
        }
    }
}

// ---------------- fused residual add + LayerNorm ----------------
__global__ void add_ln_kernel(const float* __restrict__ a, const float* __restrict__ bsrc,
                              const float* __restrict__ g, const float* __restrict__ beta,
                              float* __restrict__ out)
{
    const int mrow = blockIdx.x;
    const int c = threadIdx.x;
    __shared__ float red[Cc];
    const float v = a[(long)mrow * Cc + c] + bsrc[(long)mrow * Cc + c];
    red[c] = v;
    __syncthreads();
    for (int s = Cc / 2; s > 0; s >>= 1) {
        if (c < s) red[c] += red[c + s];
        __syncthreads();
    }
    const float mean = red[0] * (1.f / (float)Cc);
    __syncthreads();
    const float d = v - mean;
    red[c] = d * d;
    __syncthreads();
    for (int s = Cc / 2; s > 0; s >>= 1) {
        if (c < s) red[c] += red[c + s];
        __syncthreads();
    }
    const float var = red[0] * (1.f / (float)Cc);
    out[(long)mrow * Cc + c] = d * rsqrtf(var + 1e-5f) * g[c] + beta[c];
}

__global__ void add_lnK_kernel(const float* __restrict__ a, const float* __restrict__ pbase,
                               const float* __restrict__ cb,
                               const float* __restrict__ g, const float* __restrict__ beta,
                               float* __restrict__ out)
{
    const int mrow = blockIdx.x;
    const int c = threadIdx.x;
    __shared__ float red[Cc];
    const long off = (long)mrow * Cc + c;
    float v = a[off] + cb[c];
#pragma unroll
    for (int s = 0; s < NSPLIT; s++) v += pbase[off + (size_t)s * NELEM];
    red[c] = v;
    __syncthreads();
    for (int s = Cc / 2; s > 0; s >>= 1) {
        if (c < s) red[c] += red[c + s];
        __syncthreads();
    }
    const float mean = red[0] * (1.f / (float)Cc);
    __syncthreads();
    const float d = v - mean;
    red[c] = d * d;
    __syncthreads();
    for (int s = Cc / 2; s > 0; s >>= 1) {
        if (c < s) red[c] += red[c + s];
        __syncthreads();
    }
    const float var = red[0] * (1.f / (float)Cc);
    out[off] = d * rsqrtf(var + 1e-5f) * g[c] + beta[c];
}

// ---------------- launcher (single stream, r13-proven structure) ----------------
extern "C" void kernel_launch(void* const* d_in, const int* in_sizes, int n_in,
                              void* d_out, int out_size)
{
    const float* x        = (const float*)d_in[0];
    const float* wq_proj  = (const float*)d_in[1];
    const float* bq_proj  = (const float*)d_in[2];
    const float* wk_proj  = (const float*)d_in[3];
    const float* bk_proj  = (const float*)d_in[4];
    const float* wv_proj  = (const float*)d_in[5];
    const float* bv_proj  = (const float*)d_in[6];
    const float* wq_a     = (const float*)d_in[7];
    const float* bq_a     = (const float*)d_in[8];
    const float* wk_a     = (const float*)d_in[9];
    const float* bk_a     = (const float*)d_in[10];
    const float* wv_a     = (const float*)d_in[11];
    const float* bv_a     = (const float*)d_in[12];
    const float* wo_a     = (const float*)d_in[13];
    const float* bo_a     = (const float*)d_in[14];
    const float* conv_w   = (const float*)d_in[15];
    const float* conv_b   = (const float*)d_in[16];
    const float* ln1_g    = (const float*)d_in[17];
    const float* ln1_b    = (const float*)d_in[18];
    const float* ln2_g    = (const float*)d_in[19];
    const float* ln2_b    = (const float*)d_in[20];
    float* out = (float*)d_out;

    float* buf = nullptr;   cudaGetSymbolAddress((void**)&buf, g_buf);
    float* loc = nullptr;   cudaGetSymbolAddress((void**)&loc, g_loc);
    __nv_bfloat16 *xh, *xl, *ah, *al, *cxh, *cxl, *kvh, *kvl, *wth, *wtl, *w7h, *w7l;
    cudaGetSymbolAddress((void**)&xh,  g_x_hi);
    cudaGetSymbolAddress((void**)&xl,  g_x_lo);
    cudaGetSymbolAddress((void**)&ah,  g_act_hi);
    cudaGetSymbolAddress((void**)&al,  g_act_lo);
    cudaGetSymbolAddress((void**)&cxh, g_ctx_hi);
    cudaGetSymbolAddress((void**)&cxl, g_ctx_lo);
    cudaGetSymbolAddress((void**)&kvh, g_kvg_hi);
    cudaGetSymbolAddress((void**)&kvl, g_kvg_lo);
    cudaGetSymbolAddress((void**)&wth, g_wt_hi);
    cudaGetSymbolAddress((void**)&wtl, g_wt_lo);
    cudaGetSymbolAddress((void**)&w7h, g_w7_hi);
    cudaGetSymbolAddress((void**)&w7l, g_w7_lo);

    float* qp   = buf + 0l * NELEM;
    float* kp   = buf + 1l * NELEM;
    float* vp   = buf + 2l * NELEM;
    float* xres = buf + 3l * NELEM;
    float* q2   = buf + 4l * NELEM;
    float* k2   = buf + 5l * NELEM;
    float* v2   = buf + 6l * NELEM;
    float* rout = buf + 7l * NELEM;
    float* cnvp = buf + 8l * NELEM;
    float* qloc = loc;
    float* kloc = loc + 16 * Cc;

    // 1: all decomposition (w7 + conv weight + x) in one tight launch (2816 CTAs)
    {
        DecompArgs da;
        da.w[0] = wq_proj; da.w[1] = wk_proj; da.w[2] = wv_proj;
        da.w[3] = wq_a;    da.w[4] = wk_a;    da.w[5] = wv_a;    da.w[6] = wo_a;
        da.convw = conv_w; da.x = x;
        decomp_merged_kernel<<<2816, 256>>>(da);
    }

    // 2: q/k/v block projections
    {
        GemmSetT gs;
        for (int i = 0; i < 3; i++) {
            gs.Ah[i] = xh; gs.Al[i] = xl;
            gs.Bh[i] = w7h + i * WSZ; gs.Bl[i] = w7l + i * WSZ;
            gs.Ch[i] = ah + (long)i * NELEM; gs.Cl[i] = al + (long)i * NELEM;
        }
        gs.bias[0] = bq_proj; gs.bias[1] = bk_proj; gs.bias[2] = bv_proj;
        gs.C[0] = qp; gs.C[1] = kp; gs.C[2] = vp;
        gemm_mma_kernel<<<dim3(NROW / 128, Cc / 128, 3), 256>>>(gs);
    }

    // 3: kvg decompose + pool (3088 CTAs, tight)
    kvg_pool_kernel<<<3072 + 16, 256>>>(kp, vp, qp, kvh, kvl, qloc, kloc);

    // 4: conv via reg-pipelined mma.sync
    conv_mma_kernel<<<dim3(NROW / 128, Cc / 128, NSPLIT), 256>>>(kvh, kvl, wth, wtl, cnvp);

    // 5: attention head projections
    {
        GemmSetT gs;
        for (int i = 0; i < 3; i++) {
            gs.Ah[i] = ah + (long)i * NELEM; gs.Al[i] = al + (long)i * NELEM;
            gs.Bh[i] = w7h + (3 + i) * WSZ;  gs.Bl[i] = w7l + (3 + i) * WSZ;
            gs.Ch[i] = nullptr; gs.Cl[i] = nullptr;
        }
        gs.bias[0] = bq_a; gs.bias[1] = bk_a; gs.bias[2] = bv_a;
        gs.C[0] = q2; gs.C[1] = k2; gs.C[2] = v2;
        gemm_mma_kernel<<<dim3(NROW / 128, Cc / 128, 3), 256>>>(gs);
    }

    // 6: routed attention (routing inline; fixed-reference softmax; emits ctx hi/lo)
    attention_kernel<<<Bsz * Pp * NHh, 256>>>(q2, k2, v2, qloc, kloc, cxh, cxl);

    // 7: output projection
    {
        GemmSetT gs;
        gs.Ah[0] = cxh; gs.Al[0] = cxl;
        gs.Bh[0] = w7h + 6 * WSZ; gs.Bl[0] = w7l + 6 * WSZ;
        gs.bias[0] = bo_a;
        gs.C[0] = rout;
        gs.Ch[0] = nullptr; gs.Cl[0] = nullptr;
        for (int i = 1; i < 3; i++) {
            gs.Ah[i] = cxh; gs.Al[i] = cxl;
            gs.Bh[i] = w7h; gs.Bl[i] = w7l;
            gs.bias[i] = bo_a; gs.C[i] = rout;
            gs.Ch[i] = nullptr; gs.Cl[i] = nullptr;
        }
        gemm_mma_kernel<<<dim3(NROW / 128, Cc / 128, 1), 256>>>(gs);
    }

    // 8-9: LayerNorms
    add_ln_kernel<<<NROW, Cc>>>(x, rout, ln1_g, ln1_b, xres);
    add_lnK_kernel<<<NROW, Cc>>>(xres, cnvp, conv_b, ln2_g, ln2_b, out);
}

// round 17
// speedup vs baseline: 1.7102x; 1.0081x over previous
#include <cuda_runtime.h>
#include <cuda_bf16.h>
#include <math.h>
#include <stdint.h>

// Problem constants
#define Bsz 2
#define Hh  64
#define Ww  24
#define Cc  256
#define Pp  8
#define HP  8
#define NHh 8
#define DK  32
#define KV  4
#define NROW (Bsz*Hh*Ww)       // 3072
#define NELEM (NROW*Cc)        // 786432
#define LBLK (HP*Ww)           // 192
#define LKEY (KV*LBLK)         // 768
#define KTOT (25*Cc)           // 6400 conv K
#define NSPLIT 3
#define NCHUNK 200             // 6400 / 32
#define WSZ ((long)Cc*Cc)

#define QK_SCALE (0.17677669529663687f * 1.44269504088896340f)

// ---------------- device scratch ----------------
// fp32 slots: 0:qp 1:kp 2:vp 3:xres 4:q2 5:k2 6:v2 7:rout 8..10:conv partials
__device__ float g_buf[11u * NELEM];
__device__ float g_loc[2 * 16 * Cc];
__device__ __nv_bfloat16 g_x_hi[NELEM],   g_x_lo[NELEM];
__device__ __nv_bfloat16 g_act_hi[3u*NELEM], g_act_lo[3u*NELEM];
__device__ __nv_bfloat16 g_ctx_hi[NELEM], g_ctx_lo[NELEM];
__device__ __nv_bfloat16 g_kvg_hi[NELEM], g_kvg_lo[NELEM];
__device__ __nv_bfloat16 g_wt_hi[Cc * KTOT], g_wt_lo[Cc * KTOT];
__device__ __nv_bfloat16 g_w7_hi[7u*Cc*Cc], g_w7_lo[7u*Cc*Cc];

// ---------------- packed f32x2 helpers ----------------
__device__ __forceinline__ unsigned long long pk2(float lo, float hi) {
    unsigned long long r;
    asm("mov.b64 %0, {%1, %2};" : "=l"(r)
        : "r"(__float_as_uint(lo)), "r"(__float_as_uint(hi)));
    return r;
}
__device__ __forceinline__ unsigned long long ffma2(unsigned long long a,
                                                    unsigned long long b,
                                                    unsigned long long c) {
    unsigned long long d;
    asm("fma.rn.f32x2 %0, %1, %2, %3;" : "=l"(d) : "l"(a), "l"(b), "l"(c));
    return d;
}
__device__ __forceinline__ unsigned long long fadd2(unsigned long long a,
                                                    unsigned long long b) {
    unsigned long long d;
    asm("add.rn.f32x2 %0, %1, %2;" : "=l"(d) : "l"(a), "l"(b));
    return d;
}
__device__ __forceinline__ float2 upk2(unsigned long long v) {
    unsigned int lo, hi;
    asm("mov.b64 {%0, %1}, %2;" : "=r"(lo), "=r"(hi) : "l"(v));
    return make_float2(__uint_as_float(lo), __uint_as_float(hi));
}
__device__ __forceinline__ float ex2f(float x) {
    float r;
    asm("ex2.approx.ftz.f32 %0, %1;" : "=f"(r) : "f"(x));
    return r;
}

// ---------------- warp MMA helpers ----------------
__device__ __forceinline__ uint32_t smem_u32(const void* p) {
    uint32_t a;
    asm("{ .reg .u64 t; cvta.to.shared.u64 t, %1; cvt.u32.u64 %0, t; }"
        : "=r"(a) : "l"(p));
    return a;
}
#define SWZ64(o) ((o) ^ (((o) >> 3) & 0x30))

__device__ __forceinline__ void ldsm4(uint32_t* r, uint32_t addr) {
    asm volatile("ldmatrix.sync.aligned.m8n8.x4.shared.b16 {%0,%1,%2,%3}, [%4];"
                 : "=r"(r[0]), "=r"(r[1]), "=r"(r[2]), "=r"(r[3]) : "r"(addr));
}
__device__ __forceinline__ void mma_bf16(float* c, const uint32_t* a, const uint32_t* b) {
    asm volatile(
        "mma.sync.aligned.m16n8k16.row.col.f32.bf16.bf16.f32 "
        "{%0,%1,%2,%3}, {%4,%5,%6,%7}, {%8,%9}, {%0,%1,%2,%3};"
        : "+f"(c[0]), "+f"(c[1]), "+f"(c[2]), "+f"(c[3])
        : "r"(a[0]), "r"(a[1]), "r"(a[2]), "r"(a[3]), "r"(b[0]), "r"(b[1]));
}

// ================= tensor-core projection GEMM (hi/lo split), r5/r10-proven ===========
struct GemmSetT {
    const __nv_bfloat16 *Ah[3], *Al[3], *Bh[3], *Bl[3];
    const float* bias[3];
    float* C[3];
    __nv_bfloat16 *Ch[3], *Cl[3];   // optional (null => skip)
};

__global__ __launch_bounds__(256, 1)
void gemm_mma_kernel(GemmSetT gs)
{
    __shared__ char smem[32768];
    const uint32_t sb = smem_u32(smem);
    const uint32_t A_HI = sb, A_LO = sb + 8192, B_HI = sb + 16384, B_LO = sb + 24576;

    const int z = blockIdx.z;
    const __nv_bfloat16* __restrict__ Ah = gs.Ah[z];
    const __nv_bfloat16* __restrict__ Al = gs.Al[z];
    const __nv_bfloat16* __restrict__ Bh = gs.Bh[z];
    const __nv_bfloat16* __restrict__ Bl = gs.Bl[z];
    const float* __restrict__ bias = gs.bias[z];
    float* __restrict__ C = gs.C[z];
    __nv_bfloat16* __restrict__ Ch = gs.Ch[z];
    __nv_bfloat16* __restrict__ Cl = gs.Cl[z];

    const int tid  = threadIdx.x;
    const int wid  = tid >> 5;
    const int lane = tid & 31;
    const int m0 = blockIdx.x * 128;
    const int n0 = blockIdx.y * 128;
    const int wm = wid & 3;
    const int wn = wid >> 2;

    int l_row[2], l_seg[2];
#pragma unroll
    for (int i = 0; i < 2; i++) {
        const int idx = tid + 256 * i;
        l_row[i] = idx >> 2;
        l_seg[i] = idx & 3;
    }

    float acc[2][8][4];
#pragma unroll
    for (int i = 0; i < 2; i++)
#pragma unroll
        for (int j = 0; j < 8; j++)
#pragma unroll
            for (int q = 0; q < 4; q++) acc[i][j][q] = 0.f;

    uint4 rAh[2], rAl[2], rBh[2], rBl[2];
#pragma unroll
    for (int i = 0; i < 2; i++) {
        const long aoff = (long)(m0 + l_row[i]) * Cc + l_seg[i] * 8;
        rAh[i] = *(const uint4*)(Ah + aoff);
        rAl[i] = *(const uint4*)(Al + aoff);
        const long boff = (long)(n0 + l_row[i]) * Cc + l_seg[i] * 8;
        rBh[i] = *(const uint4*)(Bh + boff);
        rBl[i] = *(const uint4*)(Bl + boff);
    }

    for (int c = 0; c < 8; c++) {
        __syncthreads();
#pragma unroll
        for (int i = 0; i < 2; i++) {
            const uint32_t so = SWZ64((uint32_t)(l_row[i] * 64 + l_seg[i] * 16));
            *(uint4*)(smem + so)         = rAh[i];
            *(uint4*)(smem + 8192 + so)  = rAl[i];
            *(uint4*)(smem + 16384 + so) = rBh[i];
            *(uint4*)(smem + 24576 + so) = rBl[i];
        }
        __syncthreads();

        if (c + 1 < 8) {
            const int kb = (c + 1) * 32;
#pragma unroll
            for (int i = 0; i < 2; i++) {
                const long aoff = (long)(m0 + l_row[i]) * Cc + kb + l_seg[i] * 8;
                rAh[i] = *(const uint4*)(Ah + aoff);
                rAl[i] = *(const uint4*)(Al + aoff);
                const long boff = (long)(n0 + l_row[i]) * Cc + kb + l_seg[i] * 8;
                rBh[i] = *(const uint4*)(Bh + boff);
                rBl[i] = *(const uint4*)(Bl + boff);
            }
        }

#pragma unroll
        for (int kst = 0; kst < 2; kst++) {
            uint32_t ahi[2][4], alo[2][4];
#pragma unroll
            for (int mh = 0; mh < 2; mh++) {
                const int tile = lane >> 3;
                const int row = wm * 32 + mh * 16 + ((tile & 1) << 3) + (lane & 7);
                const int unit = kst * 2 + (tile >> 1);
                const uint32_t so = SWZ64((uint32_t)(row * 64 + unit * 16));
                ldsm4(ahi[mh], A_HI + so);
                ldsm4(alo[mh], A_LO + so);
            }
            uint32_t bhi[8][2], blo[8][2];
#pragma unroll
            for (int ng = 0; ng < 4; ng++) {
                const int tile = lane >> 3;
                const int row = wn * 64 + ng * 16 + ((tile >> 1) << 3) + (lane & 7);
                const int unit = kst * 2 + (tile & 1);
                const uint32_t so = SWZ64((uint32_t)(row * 64 + unit * 16));
                uint32_t th[4], tl[4];
                ldsm4(th, B_HI + so);
                ldsm4(tl, B_LO + so);
                bhi[ng * 2][0] = th[0]; bhi[ng * 2][1] = th[1];
                bhi[ng * 2 + 1][0] = th[2]; bhi[ng * 2 + 1][1] = th[3];
                blo[ng * 2][0] = tl[0]; blo[ng * 2][1] = tl[1];
                blo[ng * 2 + 1][0] = tl[2]; blo[ng * 2 + 1][1] = tl[3];
            }
#pragma unroll
            for (int mh = 0; mh < 2; mh++)
#pragma unroll
                for (int nt = 0; nt < 8; nt++) {
                    mma_bf16(acc[mh][nt], ahi[mh], bhi[nt]);
                    mma_bf16(acc[mh][nt], alo[mh], bhi[nt]);
                    mma_bf16(acc[mh][nt], ahi[mh], blo[nt]);
                }
        }
    }

    // epilogue: bias + fp32 C + optional bf16 hi/lo decompose
#pragma unroll
    for (int mh = 0; mh < 2; mh++) {
        const int mrow = m0 + wm * 32 + mh * 16 + (lane >> 2);
#pragma unroll
        for (int nt = 0; nt < 8; nt++) {
            const int n = n0 + wn * 64 + nt * 8 + (lane & 3) * 2;
            const float2 bi = *(const float2*)&bias[n];
            const float v0 = acc[mh][nt][0] + bi.x;
            const float v1 = acc[mh][nt][1] + bi.y;
            const float v2 = acc[mh][nt][2] + bi.x;
            const float v3 = acc[mh][nt][3] + bi.y;
            const size_t o0 = (size_t)mrow * Cc + n;
            const size_t o1 = (size_t)(mrow + 8) * Cc + n;
            *(float2*)&C[o0] = make_float2(v0, v1);
            *(float2*)&C[o1] = make_float2(v2, v3);
            if (Ch) {
                const __nv_bfloat16 h0 = __float2bfloat16(v0);
                const __nv_bfloat16 h1 = __float2bfloat16(v1);
                const __nv_bfloat16 h2 = __float2bfloat16(v2);
                const __nv_bfloat16 h3 = __float2bfloat16(v3);
                *(__nv_bfloat162*)&Ch[o0] = __nv_bfloat162(h0, h1);
                *(__nv_bfloat162*)&Ch[o1] = __nv_bfloat162(h2, h3);
                *(__nv_bfloat162*)&Cl[o0] = __nv_bfloat162(
                    __float2bfloat16(v0 - __bfloat162float(h0)),
                    __float2bfloat16(v1 - __bfloat162float(h1)));
                *(__nv_bfloat162*)&Cl[o1] = __nv_bfloat162(
                    __float2bfloat16(v2 - __bfloat162float(h2)),
                    __float2bfloat16(v3 - __bfloat162float(h3)));
            }
        }
    }
}

// ---------------- conv implicit GEMM, 128x128 tile, reg-pipelined K32 (r5/r10-proven) ------
__global__ __launch_bounds__(256, 1)
void conv_mma_kernel(const __nv_bfloat16* __restrict__ a_hi,
                     const __nv_bfloat16* __restrict__ a_lo,
                     const __nv_bfloat16* __restrict__ b_hi,
                     const __nv_bfloat16* __restrict__ b_lo,
                     float* __restrict__ part)
{
    __shared__ char smem[32768];
    const uint32_t sb = smem_u32(smem);
    const uint32_t A_HI = sb, A_LO = sb + 8192, B_HI = sb + 16384, B_LO = sb + 24576;

    const int tid  = threadIdx.x;
    const int wid  = tid >> 5;
    const int lane = tid & 31;
    const int m0 = blockIdx.x * 128;
    const int n0 = blockIdx.y * 128;
    const int z  = blockIdx.z;
    const int cbeg = (z * NCHUNK) / 3;
    const int cend = ((z + 1) * NCHUNK) / 3;

    const int wm = wid & 3;
    const int wn = wid >> 2;

    int a_row[2], a_seg[2], a_h[2], a_w[2];
    long a_base[2];
    int b_rw[2], b_sg[2];
#pragma unroll
    for (int i = 0; i < 2; i++) {
        const int idx = tid + 256 * i;
        a_row[i] = idx >> 2;
        a_seg[i] = idx & 3;
        const int m = m0 + a_row[i];
        const int b = m / (Hh * Ww);
        a_h[i] = (m / Ww) % Hh;
        a_w[i] = m % Ww;
        a_base[i] = (long)b * Hh * Ww * Cc;
        b_rw[i] = idx >> 2;
        b_sg[i] = idx & 3;
    }

    float acc[2][8][4];
#pragma unroll
    for (int i = 0; i < 2; i++)
#pragma unroll
        for (int j = 0; j < 8; j++)
#pragma unroll
            for (int q = 0; q < 4; q++) acc[i][j][q] = 0.f;

    uint4 rAh[2], rAl[2], rBh[2], rBl[2];
    {
        const int kb = cbeg * 32;
        const int patch = kb >> 8;
        const int kh = patch / 5, kw = patch % 5;
        const int ci0 = kb & 255;
#pragma unroll
        for (int i = 0; i < 2; i++) {
            const int hh = a_h[i] + kh - 2;
            const int ww = a_w[i] + kw - 2;
            if (hh >= 0 && hh < Hh && ww >= 0 && ww < Ww) {
                const long off = a_base[i] + ((long)hh * Ww + ww) * Cc + ci0 + a_seg[i] * 8;
                rAh[i] = *(const uint4*)(a_hi + off);
                rAl[i] = *(const uint4*)(a_lo + off);
            } else {
                rAh[i] = make_uint4(0, 0, 0, 0);
                rAl[i] = make_uint4(0, 0, 0, 0);
            }
            const long boff = (long)(n0 + b_rw[i]) * KTOT + kb + b_sg[i] * 8;
            rBh[i] = *(const uint4*)(b_hi + boff);
            rBl[i] = *(const uint4*)(b_lo + boff);
        }
    }

    for (int c = cbeg; c < cend; c++) {
        __syncthreads();
#pragma unroll
        for (int i = 0; i < 2; i++) {
            const uint32_t soA = SWZ64((uint32_t)(a_row[i] * 64 + a_seg[i] * 16));
            *(uint4*)(smem + soA)        = rAh[i];
            *(uint4*)(smem + 8192 + soA) = rAl[i];
            const uint32_t soB = SWZ64((uint32_t)(b_rw[i] * 64 + b_sg[i] * 16));
            *(uint4*)(smem + 16384 + soB) = rBh[i];
            *(uint4*)(smem + 24576 + soB) = rBl[i];
        }
        __syncthreads();

        if (c + 1 < cend) {
            const int kb = (c + 1) * 32;
            const int patch = kb >> 8;
            const int kh = patch / 5, kw = patch % 5;
            const int ci0 = kb & 255;
#pragma unroll
            for (int i = 0; i < 2; i++) {
                const int hh = a_h[i] + kh - 2;
                const int ww = a_w[i] + kw - 2;
                if (hh >= 0 && hh < Hh && ww >= 0 && ww < Ww) {
                    const long off = a_base[i] + ((long)hh * Ww + ww) * Cc + ci0 + a_seg[i] * 8;
                    rAh[i] = *(const uint4*)(a_hi + off);
                    rAl[i] = *(const uint4*)(a_lo + off);
                } else {
                    rAh[i] = make_uint4(0, 0, 0, 0);
                    rAl[i] = make_uint4(0, 0, 0, 0);
                }
                const long boff = (long)(n0 + b_rw[i]) * KTOT + kb + b_sg[i] * 8;
                rBh[i] = *(const uint4*)(b_hi + boff);
                rBl[i] = *(const uint4*)(b_lo + boff);
            }
        }

#pragma unroll
        for (int kst = 0; kst < 2; kst++) {
            uint32_t ahi[2][4], alo[2][4];
#pragma unroll
            for (int mh = 0; mh < 2; mh++) {
                const int tile = lane >> 3;
                const int row = wm * 32 + mh * 16 + ((tile & 1) << 3) + (lane & 7);
                const int unit = kst * 2 + (tile >> 1);
                const uint32_t so = SWZ64((uint32_t)(row * 64 + unit * 16));
                ldsm4(ahi[mh], A_HI + so);
                ldsm4(alo[mh], A_LO + so);
            }
            uint32_t bhi[8][2], blo[8][2];
#pragma unroll
            for (int ng = 0; ng < 4; ng++) {
                const int tile = lane >> 3;
                const int row = wn * 64 + ng * 16 + ((tile >> 1) << 3) + (lane & 7);
                const int unit = kst * 2 + (tile & 1);
                const uint32_t so = SWZ64((uint32_t)(row * 64 + unit * 16));
                uint32_t th[4], tl[4];
                ldsm4(th, B_HI + so);
                ldsm4(tl, B_LO + so);
                bhi[ng * 2][0] = th[0]; bhi[ng * 2][1] = th[1];
                bhi[ng * 2 + 1][0] = th[2]; bhi[ng * 2 + 1][1] = th[3];
                blo[ng * 2][0] = tl[0]; blo[ng * 2][1] = tl[1];
                blo[ng * 2 + 1][0] = tl[2]; blo[ng * 2 + 1][1] = tl[3];
            }
#pragma unroll
            for (int mh = 0; mh < 2; mh++)
#pragma unroll
                for (int nt = 0; nt < 8; nt++) {
                    mma_bf16(acc[mh][nt], ahi[mh], bhi[nt]);
                    mma_bf16(acc[mh][nt], alo[mh], bhi[nt]);
                    mma_bf16(acc[mh][nt], ahi[mh], blo[nt]);
                }
        }
    }

    float* base = part + (size_t)z * NELEM;
#pragma unroll
    for (int mh = 0; mh < 2; mh++) {
        const int mrow = m0 + wm * 32 + mh * 16 + (lane >> 2);
#pragma unroll
        for (int nt = 0; nt < 8; nt++) {
            const int n = n0 + wn * 64 + nt * 8 + (lane & 3) * 2;
            *(float2*)&base[(size_t)mrow * Cc + n] =
                make_float2(acc[mh][nt][0], acc[mh][nt][1]);
            *(float2*)&base[(size_t)(mrow + 8) * Cc + n] =
                make_float2(acc[mh][nt][2], acc[mh][nt][3]);
        }
    }
}

// ---------------- merged decompose: w7 (448) + conv weight (1600) + x (768) ----------------
struct DecompArgs {
    const float* w[7];
    const float* convw;
    const float* x;
};

__global__ void decomp_merged_kernel(DecompArgs da)
{
    const int blk = blockIdx.x;
    const int tid = threadIdx.x;
    const int tx = tid & 31, ty = tid >> 5;

    if (blk < 448) {
        const int z = blk >> 6;
        const int rem = blk & 63;
        const int k0 = (rem & 7) * 32;
        const int n0 = (rem >> 3) * 32;
        const float* __restrict__ w = da.w[z];
        const long zo = (long)z * WSZ;
        __shared__ float tile[32][33];
#pragma unroll
        for (int i = 0; i < 4; i++)
            tile[ty + i * 8][tx] = w[(long)(k0 + ty + i * 8) * Cc + n0 + tx];
        __syncthreads();
#pragma unroll
        for (int i = 0; i < 4; i++) {
            const float v = tile[tx][ty + i * 8];
            const __nv_bfloat16 h = __float2bfloat16(v);
            const long o = zo + (long)(n0 + ty + i * 8) * Cc + k0 + tx;
            g_w7_hi[o] = h;
            g_w7_lo[o] = __float2bfloat16(v - __bfloat162float(h));
        }
    } else if (blk < 2048) {
        const int i2 = blk - 448;
        const int k0 = (i2 % 200) * 32;
        const int n0 = (i2 / 200) * 32;
        __shared__ float tile[32][33];
#pragma unroll
        for (int i = 0; i < 4; i++)
            tile[ty + i * 8][tx] = da.convw[(long)(k0 + ty + i * 8) * Cc + n0 + tx];
        __syncthreads();
#pragma unroll
        for (int i = 0; i < 4; i++) {
            const float v = tile[tx][ty + i * 8];
            const __nv_bfloat16 h = __float2bfloat16(v);
            const long o = (long)(n0 + ty + i * 8) * KTOT + k0 + tx;
            g_wt_hi[o] = h;
            g_wt_lo[o] = __float2bfloat16(v - __bfloat162float(h));
        }
    } else {
        const int idx = (blk - 2048) * 256 + tid;
        if (idx < NELEM / 4) {
            const float4 v = ((const float4*)da.x)[idx];
            const __nv_bfloat16 h0 = __float2bfloat16(v.x), h1 = __float2bfloat16(v.y);
            const __nv_bfloat16 h2 = __float2bfloat16(v.z), h3 = __float2bfloat16(v.w);
            ((__nv_bfloat162*)g_x_hi)[idx * 2]     = __nv_bfloat162(h0, h1);
            ((__nv_bfloat162*)g_x_hi)[idx * 2 + 1] = __nv_bfloat162(h2, h3);
            ((__nv_bfloat162*)g_x_lo)[idx * 2]     = __nv_bfloat162(
                __float2bfloat16(v.x - __bfloat162float(h0)),
                __float2bfloat16(v.y - __bfloat162float(h1)));
            ((__nv_bfloat162*)g_x_lo)[idx * 2 + 1] = __nv_bfloat162(
                __float2bfloat16(v.z - __bfloat162float(h2)),
                __float2bfloat16(v.w - __bfloat162float(h3)));
        }
    }
}

// ---------------- merged: decompose kvg = kp+vp (3072 CTAs) + pool (16 CTAs) ----------------
__global__ void kvg_pool_kernel(const float* __restrict__ kp, const float* __restrict__ vp,
                                const float* __restrict__ qp,
                                __nv_bfloat16* __restrict__ hi, __nv_bfloat16* __restrict__ lo,
                                float* __restrict__ qloc, float* __restrict__ kloc)
{
    const int blk = blockIdx.x;
    const int tid = threadIdx.x;
    if (blk < 3072) {
        const int i = blk * 256 + tid;
        const float v = kp[i] + vp[i];
        const __nv_bfloat16 h = __float2bfloat16(v);
        hi[i] = h;
        lo[i] = __float2bfloat16(v - __bfloat162float(h));
    } else {
        const int bp = blk - 3072;
        const float* qb = qp + (long)bp * LBLK * Cc + tid;
        const float* kb = kp + (long)bp * LBLK * Cc + tid;
        float sq = 0.f, sk = 0.f;
        for (int i = 0; i < LBLK; i++) { sq += qb[i * Cc]; sk += kb[i * Cc]; }
        qloc[bp * Cc + tid] = sq * (1.f / (float)LBLK);
        kloc[bp * Cc + tid] = sk * (1.f / (float)LBLK);
    }
}

// ---------------- attention: inline routing + fixed-ref softmax + LDS.128 ----------------
#define KCHUNK 128
__global__ void attention_kernel(const float* __restrict__ q2,
                                 const float* __restrict__ k2,
                                 const float* __restrict__ v2,
                                 const float* __restrict__ qloc,
                                 const float* __restrict__ kloc,
                                 __nv_bfloat16* __restrict__ ctx_hi,
                                 __nv_bfloat16* __restrict__ ctx_lo)
{
    __shared__ float Ks[KCHUNK * DK];
    __shared__ float Vs[KCHUNK * DK];
    __shared__ float Sl[8];
    __shared__ float K0[DK];
    __shared__ int   Rs[KV];

    const int blk = blockIdx.x;
    const int h = blk % NHh;
    const int p = (blk / NHh) % Pp;
    const int b = blk / (NHh * Pp);
    const int tid = threadIdx.x;
    const int wid = tid >> 5;
    const int lane = tid & 31;

    // inline routing
    {
        const float* q = qloc + (b * Pp + p) * Cc;
        const float* k = kloc + (b * Pp + wid) * Cc;
        float partial = 0.f;
#pragma unroll
        for (int c = lane; c < Cc; c += 32) partial += q[c] * k[c];
#pragma unroll
        for (int o = 16; o; o >>= 1) partial += __shfl_xor_sync(0xffffffff, partial, o);
        if (lane == 0) Sl[wid] = partial;
        __syncthreads();
        if (tid == 0) {
            bool used[8] = {};
            for (int t = 0; t < KV; t++) {
                int best = 0; float bv = -1e30f;
                for (int j = 0; j < Pp; j++)
                    if (!used[j] && Sl[j] > bv) { bv = Sl[j]; best = j; }
                used[best] = true;
                Rs[t] = best;
            }
        }
    }
    __syncthreads();

    // stage key0's K row (first gathered key) for the reference score
    if (tid < DK) {
        const long k0base = ((long)((b * Pp + Rs[0]) * LBLK)) * Cc + h * DK;
        K0[tid] = k2[k0base + tid];
    }

    const bool active = (tid < LBLK);
    unsigned long long qv2[DK / 2], acc2[DK / 2];
    float M = 0.f, l = 0.f;
    if (active) {
        const float* qrow = q2 + ((long)((b * Pp + p) * LBLK + tid)) * Cc + h * DK;
#pragma unroll
        for (int d2 = 0; d2 < DK / 2; d2++) {
            qv2[d2] = pk2(qrow[2 * d2] * QK_SCALE, qrow[2 * d2 + 1] * QK_SCALE);
            acc2[d2] = 0ull;
        }
    }
    __syncthreads();
    if (active) {
        // M = s_0 = q . k0 (packed dot, LDS.128)
        const ulonglong2* k0p = (const ulonglong2*)K0;
        unsigned long long s0 = 0ull, s1 = 0ull, s2 = 0ull, s3 = 0ull;
#pragma unroll
        for (int j = 0; j < 8; j += 2) {
            const ulonglong2 ka = k0p[j];
            const ulonglong2 kb = k0p[j + 1];
            s0 = ffma2(qv2[2 * j + 0], ka.x, s0);
            s1 = ffma2(qv2[2 * j + 1], ka.y, s1);
            s2 = ffma2(qv2[2 * j + 2], kb.x, s2);
            s3 = ffma2(qv2[2 * j + 3], kb.y, s3);
        }
        const unsigned long long st = fadd2(fadd2(s0, s1), fadd2(s2, s3));
        const float2 f = upk2(st);
        M = f.x + f.y;
    }

    for (int ch = 0; ch < LKEY / KCHUNK; ch++) {
        __syncthreads();
        const int kg0 = ch * KCHUNK;
        for (int i = tid; i < KCHUNK * (DK / 4); i += blockDim.x) {
            const int row = i >> 3;
            const int d4  = (i & 7) * 4;
            const int kg  = kg0 + row;
            const int ks  = kg / LBLK;
            const int rr  = kg - ks * LBLK;
            const int r   = Rs[ks];
            const long base = ((long)(b * Pp + r) * LBLK + rr) * Cc + h * DK + d4;
            *(float4*)&Ks[row * DK + d4] = *(const float4*)&k2[base];
            *(float4*)&Vs[row * DK + d4] = *(const float4*)&v2[base];
        }
        __syncthreads();
        if (active) {
            for (int k = 0; k < KCHUNK; k++) {
                // QK dot via 4x LDS.128
                const ulonglong2* kr2 = (const ulonglong2*)&Ks[k * DK];
                unsigned long long s0 = 0ull, s1 = 0ull, s2 = 0ull, s3 = 0ull;
#pragma unroll
                for (int j = 0; j < 8; j += 2) {
                    const ulonglong2 ka = kr2[j];
                    const ulonglong2 kb = kr2[j + 1];
                    s0 = ffma2(qv2[2 * j + 0], ka.x, s0);
                    s1 = ffma2(qv2[2 * j + 1], ka.y, s1);
                    s2 = ffma2(qv2[2 * j + 2], kb.x, s2);
                    s3 = ffma2(qv2[2 * j + 3], kb.y, s3);
                }
                const unsigned long long st = fadd2(fadd2(s0, s1), fadd2(s2, s3));
                const float2 f = upk2(st);
                const float s = (f.x + f.y) - M;
                const float pe = ex2f(s);
                l += pe;
                const unsigned long long pp = pk2(pe, pe);
                // PV update via 8x LDS.128
                const ulonglong2* vr2 = (const ulonglong2*)&Vs[k * DK];
#pragma unroll
                for (int j = 0; j < 8; j++) {
                    const ulonglong2 vv = vr2[j];
                    acc2[2 * j]     = ffma2(pp, vv.x, acc2[2 * j]);
                    acc2[2 * j + 1] = ffma2(pp, vv.y, acc2[2 * j + 1]);
                }
            }
        }
    }

    if (active) {
        const float inv = 1.0f / l;
        const long base = ((long)((b * Pp + p) * LBLK + tid)) * Cc + h * DK;
#pragma unroll
        for (int d2 = 0; d2 < DK / 2; d2++) {
            float2 f = upk2(acc2[d2]);
            const float v0 = f.x * inv, v1 = f.y * inv;
            const __nv_bfloat16 h0 = __float2bfloat16(v0);
            const __nv_bfloat16 h1 = __float2bfloat16(v1);
            *(__nv_bfloat162*)&ctx_hi[base + 2 * d2] = __nv_bfloat162(h0, h1);
            *(__nv_bfloat162*)&ctx_lo[base + 2 * d2] = __nv_bfloat162(
                __float2bfloat16(v0 - __bfloat162float(h0)),
                __float2bfloat16(v1 - __bfloat162float(h1)));
        }
    }
}

// ---------------- fused residual add + LayerNorm ----------------
__global__ void add_ln_kernel(const float* __restrict__ a, const float* __restrict__ bsrc,
                              const float* __restrict__ g, const float* __restrict__ beta,
                              float* __restrict__ out)
{
    const int mrow = blockIdx.x;
    const int c = threadIdx.x;
    __shared__ float red[Cc];
    const float v = a[(long)mrow * Cc + c] + bsrc[(long)mrow * Cc + c];
    red[c] = v;
    __syncthreads();
    for (int s = Cc / 2; s > 0; s >>= 1) {
        if (c < s) red[c] += red[c + s];
        __syncthreads();
    }
    const float mean = red[0] * (1.f / (float)Cc);
    __syncthreads();
    const float d = v - mean;
    red[c] = d * d;
    __syncthreads();
    for (int s = Cc / 2; s > 0; s >>= 1) {
        if (c < s) red[c] += red[c + s];
        __syncthreads();
    }
    const float var = red[0] * (1.f / (float)Cc);
    out[(long)mrow * Cc + c] = d * rsqrtf(var + 1e-5f) * g[c] + beta[c];
}

__global__ void add_lnK_kernel(const float* __restrict__ a, const float* __restrict__ pbase,
                               const float* __restrict__ cb,
                               const float* __restrict__ g, const float* __restrict__ beta,
                               float* __restrict__ out)
{
    const int mrow = blockIdx.x;
    const int c = threadIdx.x;
    __shared__ float red[Cc];
    const long off = (long)mrow * Cc + c;
    float v = a[off] + cb[c];
#pragma unroll
    for (int s = 0; s < NSPLIT; s++) v += pbase[off + (size_t)s * NELEM];
    red[c] = v;
    __syncthreads();
    for (int s = Cc / 2; s > 0; s >>= 1) {
        if (c < s) red[c] += red[c + s];
        __syncthreads();
    }
    const float mean = red[0] * (1.f / (float)Cc);
    __syncthreads();
    const float d = v - mean;
    red[c] = d * d;
    __syncthreads();
    for (int s = Cc / 2; s > 0; s >>= 1) {
        if (c < s) red[c] += red[c + s];
        __syncthreads();
    }
    const float var = red[0] * (1.f / (float)Cc);
    out[off] = d * rsqrtf(var + 1e-5f) * g[c] + beta[c];
}

// ---------------- launcher (single stream, r13-proven structure) ----------------
extern "C" void kernel_launch(void* const* d_in, const int* in_sizes, int n_in,
                              void* d_out, int out_size)
{
    const float* x        = (const float*)d_in[0];
    const float* wq_proj  = (const float*)d_in[1];
    const float* bq_proj  = (const float*)d_in[2];
    const float* wk_proj  = (const float*)d_in[3];
    const float* bk_proj  = (const float*)d_in[4];
    const float* wv_proj  = (const float*)d_in[5];
    const float* bv_proj  = (const float*)d_in[6];
    const float* wq_a     = (const float*)d_in[7];
    const float* bq_a     = (const float*)d_in[8];
    const float* wk_a     = (const float*)d_in[9];
    const float* bk_a     = (const float*)d_in[10];
    const float* wv_a     = (const float*)d_in[11];
    const float* bv_a     = (const float*)d_in[12];
    const float* wo_a     = (const float*)d_in[13];
    const float* bo_a     = (const float*)d_in[14];
    const float* conv_w   = (const float*)d_in[15];
    const float* conv_b   = (const float*)d_in[16];
    const float* ln1_g    = (const float*)d_in[17];
    const float* ln1_b    = (const float*)d_in[18];
    const float* ln2_g    = (const float*)d_in[19];
    const float* ln2_b    = (const float*)d_in[20];
    float* out = (float*)d_out;

    float* buf = nullptr;   cudaGetSymbolAddress((void**)&buf, g_buf);
    float* loc = nullptr;   cudaGetSymbolAddress((void**)&loc, g_loc);
    __nv_bfloat16 *xh, *xl, *ah, *al, *cxh, *cxl, *kvh, *kvl, *wth, *wtl, *w7h, *w7l;
    cudaGetSymbolAddress((void**)&xh,  g_x_hi);
    cudaGetSymbolAddress((void**)&xl,  g_x_lo);
    cudaGetSymbolAddress((void**)&ah,  g_act_hi);
    cudaGetSymbolAddress((void**)&al,  g_act_lo);
    cudaGetSymbolAddress((void**)&cxh, g_ctx_hi);
    cudaGetSymbolAddress((void**)&cxl, g_ctx_lo);
    cudaGetSymbolAddress((void**)&kvh, g_kvg_hi);
    cudaGetSymbolAddress((void**)&kvl, g_kvg_lo);
    cudaGetSymbolAddress((void**)&wth, g_wt_hi);
    cudaGetSymbolAddress((void**)&wtl, g_wt_lo);
    cudaGetSymbolAddress((void**)&w7h, g_w7_hi);
    cudaGetSymbolAddress((void**)&w7l, g_w7_lo);

    float* qp   = buf + 0l * NELEM;
    float* kp   = buf + 1l * NELEM;
    float* vp   = buf + 2l * NELEM;
    float* xres = buf + 3l * NELEM;
    float* q2   = buf + 4l * NELEM;
    float* k2   = buf + 5l * NELEM;
    float* v2   = buf + 6l * NELEM;
    float* rout = buf + 7l * NELEM;
    float* cnvp = buf + 8l * NELEM;
    float* qloc = loc;
    float* kloc = loc + 16 * Cc;

    // 1: all decomposition (w7 + conv weight + x) in one tight launch (2816 CTAs)
    {
        DecompArgs da;
        da.w[0] = wq_proj; da.w[1] = wk_proj; da.w[2] = wv_proj;
        da.w[3] = wq_a;    da.w[4] = wk_a;    da.w[5] = wv_a;    da.w[6] = wo_a;
        da.convw = conv_w; da.x = x;
        decomp_merged_kernel<<<2816, 256>>>(da);
    }

    // 2: q/k/v block projections
    {
        GemmSetT gs;
        for (int i = 0; i < 3; i++) {
            gs.Ah[i] = xh; gs.Al[i] = xl;
            gs.Bh[i] = w7h + i * WSZ; gs.Bl[i] = w7l + i * WSZ;
            gs.Ch[i] = ah + (long)i * NELEM; gs.Cl[i] = al + (long)i * NELEM;
        }
        gs.bias[0] = bq_proj; gs.bias[1] = bk_proj; gs.bias[2] = bv_proj;
        gs.C[0] = qp; gs.C[1] = kp; gs.C[2] = vp;
        gemm_mma_kernel<<<dim3(NROW / 128, Cc / 128, 3), 256>>>(gs);
    }

    // 3: kvg decompose + pool (3088 CTAs, tight)
    kvg_pool_kernel<<<3072 + 16, 256>>>(kp, vp, qp, kvh, kvl, qloc, kloc);

    // 4: conv via reg-pipelined mma.sync
    conv_mma_kernel<<<dim3(NROW / 128, Cc / 128, NSPLIT), 256>>>(kvh, kvl, wth, wtl, cnvp);

    // 5: attention head projections
    {
        GemmSetT gs;
        for (int i = 0; i < 3; i++) {
            gs.Ah[i] = ah + (long)i * NELEM; gs.Al[i] = al + (long)i * NELEM;
            gs.Bh[i] = w7h + (3 + i) * WSZ;  gs.Bl[i] = w7l + (3 + i) * WSZ;
            gs.Ch[i] = nullptr; gs.Cl[i] = nullptr;
        }
        gs.bias[0] = bq_a; gs.bias[1] = bk_a; gs.bias[2] = bv_a;
        gs.C[0] = q2; gs.C[1] = k2; gs.C[2] = v2;
        gemm_mma_kernel<<<dim3(NROW / 128, Cc / 128, 3), 256>>>(gs);
    }

    // 6: routed attention (routing inline; fixed-reference softmax; LDS.128 inner loop)
    attention_kernel<<<Bsz * Pp * NHh, 256>>>(q2, k2, v2, qloc, kloc, cxh, cxl);

    // 7: output projection
    {
        GemmSetT gs;
        gs.Ah[0] = cxh; gs.Al[0] = cxl;
        gs.Bh[0] = w7h + 6 * WSZ; gs.Bl[0] = w7l + 6 * WSZ;
        gs.bias[0] = bo_a;
        gs.C[0] = rout;
        gs.Ch[0] = nullptr; gs.Cl[0] = nullptr;
        for (int i = 1; i < 3; i++) {
            gs.Ah[i] = cxh; gs.Al[i] = cxl;
            gs.Bh[i] = w7h; gs.Bl[i] = w7l;
            gs.bias[i] = bo_a; gs.C[i] = rout;
            gs.Ch[i] = nullptr; gs.Cl[i] = nullptr;
        }
        gemm_mma_kernel<<<dim3(NROW / 128, Cc / 128, 1), 256>>>(gs);
    }

    // 8-9: LayerNorms
    add_ln_kernel<<<NROW, Cc>>>(x, rout, ln1_g, ln1_b, xres);
    add_lnK_kernel<<<NROW, Cc>>>(xres, cnvp, conv_b, ln2_g, ln2_b, out);
}